// round 6
// baseline (speedup 1.0000x reference)
#include <cuda_runtime.h>
#include <math.h>

// ---------------- problem constants ----------------
#define NB      2
#define TSEQ    2048
#define NDIM    2048
#define NH      16
#define NQLR    1536
#define NKVLR   512
#define NRD     64
#define NND     128
#define NVD     128
#define NTOK    (NB * TSEQ)        // 4096
#define DQK     (NND + NRD)        // 192
#define EPSV    1e-6f

// ---------------- scratch (no allocations allowed) ----------------
__device__ float g_cq   [(size_t)NTOK * NQLR];            // 25.2 MB
__device__ float g_qn   [(size_t)NTOK * NH * NND];        // 33.6 MB
__device__ float g_qr   [(size_t)NTOK * NH * NRD];        // 16.8 MB
__device__ float g_q    [(size_t)NTOK * NH * DQK];        // 50.3 MB
__device__ float g_kvraw[(size_t)NTOK * (NKVLR + NRD)];   //  9.4 MB
__device__ float g_ckv  [(size_t)NTOK * NKVLR];           //  8.4 MB
__device__ float g_kr   [(size_t)NTOK * NRD];             //  1.0 MB
__device__ float g_kv   [(size_t)NTOK * NH * (NND + NVD)];// 67.1 MB
__device__ float g_k    [(size_t)NTOK * NH * DQK];        // 50.3 MB
__device__ float g_ao   [(size_t)NTOK * NH * NVD];        // 33.6 MB

// ---------------- helpers ----------------
__device__ __forceinline__ float warp_sum(float v) {
#pragma unroll
    for (int o = 16; o; o >>= 1) v += __shfl_xor_sync(0xffffffffu, v, o);
    return v;
}

// ---------------- generic fp32 tiled GEMM: C[MxN] = A[MxK] @ B[KxN] ----------------
// Requires M%64==0, N%64==0 (N%4 for float4), K%16==0. All shapes here satisfy this.
__global__ __launch_bounds__(256) void gemm64(
    const float* __restrict__ A, const float* __restrict__ B,
    float* __restrict__ C, int M, int N, int K)
{
    __shared__ float As[16][64];   // transposed A tile: As[k][m]
    __shared__ float Bs[16][64];   // Bs[k][n]

    const int tid = threadIdx.x;
    const int m0 = blockIdx.y << 6;
    const int n0 = blockIdx.x << 6;
    const int ty = tid >> 4;          // 0..15 -> 4 output rows
    const int tx = tid & 15;          // 0..15 -> 4 output cols

    const int arow = tid >> 2;            // 0..63
    const int acol = (tid & 3) << 2;      // 0,4,8,12
    const int brow = tid >> 4;            // 0..15
    const int bcol = (tid & 15) << 2;     // 0..60

    const float* Ap = A + (size_t)(m0 + arow) * K + acol;
    const float* Bp = B + (size_t)brow * N + n0 + bcol;

    float acc[4][4];
#pragma unroll
    for (int i = 0; i < 4; i++)
#pragma unroll
        for (int j = 0; j < 4; j++) acc[i][j] = 0.f;

    for (int k0 = 0; k0 < K; k0 += 16) {
        float4 a4 = *(const float4*)(Ap + k0);
        As[acol + 0][arow] = a4.x;
        As[acol + 1][arow] = a4.y;
        As[acol + 2][arow] = a4.z;
        As[acol + 3][arow] = a4.w;
        *(float4*)&Bs[brow][bcol] = *(const float4*)(Bp + (size_t)k0 * N);
        __syncthreads();
#pragma unroll
        for (int k = 0; k < 16; k++) {
            float4 av = *(const float4*)&As[k][ty << 2];
            float4 bv = *(const float4*)&Bs[k][tx << 2];
            acc[0][0] += av.x * bv.x; acc[0][1] += av.x * bv.y;
            acc[0][2] += av.x * bv.z; acc[0][3] += av.x * bv.w;
            acc[1][0] += av.y * bv.x; acc[1][1] += av.y * bv.y;
            acc[1][2] += av.y * bv.z; acc[1][3] += av.y * bv.w;
            acc[2][0] += av.z * bv.x; acc[2][1] += av.z * bv.y;
            acc[2][2] += av.z * bv.z; acc[2][3] += av.z * bv.w;
            acc[3][0] += av.w * bv.x; acc[3][1] += av.w * bv.y;
            acc[3][2] += av.w * bv.z; acc[3][3] += av.w * bv.w;
        }
        __syncthreads();
    }

    float* Cp = C + (size_t)(m0 + (ty << 2)) * N + n0 + (tx << 2);
#pragma unroll
    for (int i = 0; i < 4; i++) {
        float4 o = make_float4(acc[i][0], acc[i][1], acc[i][2], acc[i][3]);
        *(float4*)(Cp + (size_t)i * N) = o;
    }
}

// ---------------- row-wise rmsnorm (in place), 256 threads ----------------
__global__ __launch_bounds__(256) void rmsnorm_rows(
    float* __restrict__ x, const float* __restrict__ w, int len)
{
    __shared__ float sb[8];
    float* row = x + (size_t)blockIdx.x * len;
    float ss = 0.f;
    for (int i = threadIdx.x; i < len; i += 256) { float v = row[i]; ss += v * v; }
    ss = warp_sum(ss);
    if ((threadIdx.x & 31) == 0) sb[threadIdx.x >> 5] = ss;
    __syncthreads();
    float tot = 0.f;
#pragma unroll
    for (int i = 0; i < 8; i++) tot += sb[i];
    float sc = rsqrtf(tot / (float)len + EPSV);
    for (int i = threadIdx.x; i < len; i += 256) row[i] = row[i] * sc * w[i];
}

// ---------------- build q: per-(token,head) head-rmsnorm(nope) + rope(rope) ----------------
__global__ __launch_bounds__(128) void q_build(
    const float* __restrict__ qn, const float* __restrict__ qr,
    const float* __restrict__ qhw,
    const float* __restrict__ fc, const float* __restrict__ fs,
    float* __restrict__ q)
{
    __shared__ float sb[4];
    const int token = blockIdx.y, h = blockIdx.x;
    const int t = token & (TSEQ - 1);
    const float* xn = qn + (size_t)token * NH * NND + h * NND;
    float v = xn[threadIdx.x];
    float ss = warp_sum(v * v);
    if ((threadIdx.x & 31) == 0) sb[threadIdx.x >> 5] = ss;
    __syncthreads();
    float tot = sb[0] + sb[1] + sb[2] + sb[3];
    float sc = rsqrtf(tot / (float)NND + EPSV);
    float* qo = q + ((size_t)token * NH + h) * DQK;
    qo[threadIdx.x] = v * sc * qhw[threadIdx.x];
    if (threadIdx.x < NRD / 2) {
        int i = threadIdx.x;
        const float* xr = qr + (size_t)token * NH * NRD + h * NRD;
        float a = xr[2 * i], b = xr[2 * i + 1];
        float c = fc[t * (NRD / 2) + i], s = fs[t * (NRD / 2) + i];
        qo[NND + 2 * i]     = a * c - b * s;
        qo[NND + 2 * i + 1] = a * s + b * c;
    }
}

// ---------------- kv post: rmsnorm(c_kv) and rope(k_rope shared) ----------------
__global__ __launch_bounds__(128) void kv_post(
    const float* __restrict__ kvraw, const float* __restrict__ kvw,
    const float* __restrict__ fc, const float* __restrict__ fs,
    float* __restrict__ ckv, float* __restrict__ kr)
{
    __shared__ float sb[4];
    const int token = blockIdx.x;
    const int t = token & (TSEQ - 1);
    const float* row = kvraw + (size_t)token * (NKVLR + NRD);
    float ss = 0.f;
    for (int i = threadIdx.x; i < NKVLR; i += 128) { float v = row[i]; ss += v * v; }
    ss = warp_sum(ss);
    if ((threadIdx.x & 31) == 0) sb[threadIdx.x >> 5] = ss;
    __syncthreads();
    float tot = sb[0] + sb[1] + sb[2] + sb[3];
    float sc = rsqrtf(tot / (float)NKVLR + EPSV);
    for (int i = threadIdx.x; i < NKVLR; i += 128)
        ckv[(size_t)token * NKVLR + i] = row[i] * sc * kvw[i];
    if (threadIdx.x < NRD / 2) {
        int i = threadIdx.x;
        float a = row[NKVLR + 2 * i], b = row[NKVLR + 2 * i + 1];
        float c = fc[t * (NRD / 2) + i], s = fs[t * (NRD / 2) + i];
        kr[(size_t)token * NRD + 2 * i]     = a * c - b * s;
        kr[(size_t)token * NRD + 2 * i + 1] = a * s + b * c;
    }
}

// ---------------- build k: per-(token,head) head-rmsnorm(k_nope) + copy rope ----------------
__global__ __launch_bounds__(128) void k_build(
    const float* __restrict__ kv, const float* __restrict__ khw,
    const float* __restrict__ kr, float* __restrict__ k)
{
    __shared__ float sb[4];
    const int token = blockIdx.y, h = blockIdx.x;
    const float* kn = kv + ((size_t)token * NH + h) * (NND + NVD);
    float v = kn[threadIdx.x];
    float ss = warp_sum(v * v);
    if ((threadIdx.x & 31) == 0) sb[threadIdx.x >> 5] = ss;
    __syncthreads();
    float tot = sb[0] + sb[1] + sb[2] + sb[3];
    float sc = rsqrtf(tot / (float)NND + EPSV);
    float* ko = k + ((size_t)token * NH + h) * DQK;
    ko[threadIdx.x] = v * sc * khw[threadIdx.x];
    if (threadIdx.x < NRD) ko[NND + threadIdx.x] = kr[(size_t)token * NRD + threadIdx.x];
}

// ---------------- causal flash attention ----------------
// grid: (T/32 q-tiles, B*H). block: 256 threads = 32 q-rows x 8 lanes.
// Each thread: 24-elem q segment for scores, 16 contiguous V columns for output.
__global__ __launch_bounds__(256) void attn_kernel(
    const float* __restrict__ q, const float* __restrict__ k,
    const float* __restrict__ kv, float* __restrict__ ao)
{
    __shared__ float Ks[32][DQK];   // 24 KB
    __shared__ float Vs[32][NVD];   // 16 KB
    __shared__ float Ss[32][32];    //  4 KB

    const int tid = threadIdx.x;
    const int qt = blockIdx.x;                // 0..63
    const int bh = blockIdx.y;                // 0..31
    const int b  = bh >> 4, h = bh & 15;
    const int qt0 = qt << 5;
    const int r = tid >> 3, g = tid & 7;
    const int bT = b * TSEQ;
    const float SCALE = 0.07216878364870322f; // 1/sqrt(192)

    const float* qrow = q + ((size_t)(bT + qt0 + r) * NH + h) * DQK + g * 24;
    float qseg[24];
#pragma unroll
    for (int i = 0; i < 24; i++) qseg[i] = qrow[i];

    float m = -1e30f, l = 0.f, acc[16];
#pragma unroll
    for (int c = 0; c < 16; c++) acc[c] = 0.f;

    for (int kt = 0; kt <= qt; kt++) {
        const int kt0 = kt << 5;
        // load K tile (32 x 192) coalesced
        for (int idx = tid; idx < 32 * DQK; idx += 256) {
            int row = idx / DQK, col = idx - row * DQK;
            Ks[row][col] = k[((size_t)(bT + kt0 + row) * NH + h) * DQK + col];
        }
        // load V tile (32 x 128) coalesced (v lives at offset NND inside kv rows)
        for (int idx = tid; idx < 32 * NVD; idx += 256) {
            int row = idx >> 7, col = idx & 127;
            Vs[row][col] = kv[((size_t)(bT + kt0 + row) * NH + h) * (NND + NVD) + NND + col];
        }
        __syncthreads();

        const int jmax = (kt == qt) ? r : 31;
#pragma unroll 4
        for (int j = 0; j < 32; j++) {
            float s = 0.f;
            const float* krow = &Ks[j][g * 24];
#pragma unroll
            for (int i = 0; i < 24; i++) s += qseg[i] * krow[i];
            s += __shfl_xor_sync(0xffffffffu, s, 4, 8);
            s += __shfl_xor_sync(0xffffffffu, s, 2, 8);
            s += __shfl_xor_sync(0xffffffffu, s, 1, 8);
            if (g == 0) Ss[r][j] = (j <= jmax) ? s * SCALE : -1e30f;
        }
        __syncthreads();

        float mt = -1e30f;
#pragma unroll
        for (int j = 0; j < 32; j++) mt = fmaxf(mt, Ss[r][j]);
        float mn = fmaxf(m, mt);
        float corr = __expf(m - mn);
        l *= corr;
#pragma unroll
        for (int c = 0; c < 16; c++) acc[c] *= corr;
#pragma unroll 4
        for (int j = 0; j < 32; j++) {
            float p = __expf(Ss[r][j] - mn);
            l += p;
            const float* vr = &Vs[j][g * 16];
#pragma unroll
            for (int c = 0; c < 16; c++) acc[c] += p * vr[c];
        }
        m = mn;
        __syncthreads();
    }

    const float inv = 1.f / l;
    float* op = ao + ((size_t)(bT + qt0 + r) * NH + h) * NVD + g * 16;
#pragma unroll
    for (int c = 0; c < 16; c++) op[c] = acc[c] * inv;
}

// ---------------- launch ----------------
extern "C" void kernel_launch(void* const* d_in, const int* in_sizes, int n_in,
                              void* d_out, int out_size)
{
    const float* x    = (const float*)d_in[0];
    const float* fc   = (const float*)d_in[1];
    const float* fs   = (const float*)d_in[2];
    const float* qdw  = (const float*)d_in[3];
    const float* qnw  = (const float*)d_in[4];
    const float* qunw = (const float*)d_in[5];
    const float* qurw = (const float*)d_in[6];
    const float* kdw  = (const float*)d_in[7];
    const float* kvnw = (const float*)d_in[8];
    const float* kuw  = (const float*)d_in[9];
    const float* qhw  = (const float*)d_in[10];
    const float* khw  = (const float*)d_in[11];
    const float* wow  = (const float*)d_in[12];
    float* out = (float*)d_out;

    float *p_cq, *p_qn, *p_qr, *p_q, *p_kvraw, *p_ckv, *p_kr, *p_kv, *p_k, *p_ao;
    cudaGetSymbolAddress((void**)&p_cq,    g_cq);
    cudaGetSymbolAddress((void**)&p_qn,    g_qn);
    cudaGetSymbolAddress((void**)&p_qr,    g_qr);
    cudaGetSymbolAddress((void**)&p_q,     g_q);
    cudaGetSymbolAddress((void**)&p_kvraw, g_kvraw);
    cudaGetSymbolAddress((void**)&p_ckv,   g_ckv);
    cudaGetSymbolAddress((void**)&p_kr,    g_kr);
    cudaGetSymbolAddress((void**)&p_kv,    g_kv);
    cudaGetSymbolAddress((void**)&p_k,     g_k);
    cudaGetSymbolAddress((void**)&p_ao,    g_ao);

    // c_q = x @ q_down_w ; rmsnorm
    gemm64<<<dim3(NQLR / 64, NTOK / 64), 256>>>(x, qdw, p_cq, NTOK, NQLR, NDIM);
    rmsnorm_rows<<<NTOK, 256>>>(p_cq, qnw, NQLR);

    // q projections
    gemm64<<<dim3((NH * NND) / 64, NTOK / 64), 256>>>(p_cq, qunw, p_qn, NTOK, NH * NND, NQLR);
    gemm64<<<dim3((NH * NRD) / 64, NTOK / 64), 256>>>(p_cq, qurw, p_qr, NTOK, NH * NRD, NQLR);

    // kv down
    gemm64<<<dim3((NKVLR + NRD) / 64, NTOK / 64), 256>>>(x, kdw, p_kvraw, NTOK, NKVLR + NRD, NDIM);

    // epilogues (independent of each other)
    q_build<<<dim3(NH, NTOK), 128>>>(p_qn, p_qr, qhw, fc, fs, p_q);
    kv_post<<<NTOK, 128>>>(p_kvraw, kvnw, fc, fs, p_ckv, p_kr);

    // kv up + k build
    gemm64<<<dim3((NH * (NND + NVD)) / 64, NTOK / 64), 256>>>(p_ckv, kuw, p_kv, NTOK, NH * (NND + NVD), NKVLR);
    k_build<<<dim3(NH, NTOK), 128>>>(p_kv, khw, p_kr, p_k);

    // attention
    attn_kernel<<<dim3(TSEQ / 32, NB * NH), 256>>>(p_q, p_k, p_kv, p_ao);

    // output projection
    gemm64<<<dim3(NDIM / 64, NTOK / 64), 256>>>(p_ao, wow, out, NTOK, NDIM, NH * NVD);
}

// round 7
// speedup vs baseline: 2.5857x; 2.5857x over previous
#include <cuda_runtime.h>
#include <math.h>

// ---------------- problem constants ----------------
#define NB      2
#define TSEQ    2048
#define NDIM    2048
#define NH      16
#define NQLR    1536
#define NKVLR   512
#define NRD     64
#define NND     128
#define NVD     128
#define NTOK    (NB * TSEQ)        // 4096
#define DQK     (NND + NRD)        // 192
#define EPSV    1e-6f

// ---------------- scratch (no allocations allowed) ----------------
__device__ float g_cq   [(size_t)NTOK * NQLR];
__device__ float g_qn   [(size_t)NTOK * NH * NND];
__device__ float g_qr   [(size_t)NTOK * NH * NRD];
__device__ float g_q    [(size_t)NTOK * NH * DQK];
__device__ float g_kvraw[(size_t)NTOK * (NKVLR + NRD)];
__device__ float g_ckv  [(size_t)NTOK * NKVLR];
__device__ float g_kr   [(size_t)NTOK * NRD];
__device__ float g_kv   [(size_t)NTOK * NH * (NND + NVD)];
__device__ float g_k    [(size_t)NTOK * NH * DQK];
__device__ float g_ao   [(size_t)NTOK * NH * NVD];

// ---------------- helpers ----------------
__device__ __forceinline__ float warp_sum(float v) {
#pragma unroll
    for (int o = 16; o; o >>= 1) v += __shfl_xor_sync(0xffffffffu, v, o);
    return v;
}

// ============ 128x128x16 fp32 GEMM, 256 thr, 8x8 microtile ============
// Requires M%128==0, N%128==0, K%16==0.
__global__ __launch_bounds__(256) void gemm128(
    const float* __restrict__ A, const float* __restrict__ B,
    float* __restrict__ C, int M, int N, int K)
{
    __shared__ float As[16][132];   // As[k][m] (transposed A tile)
    __shared__ float Bs[16][128];   // Bs[k][n]

    const int tid = threadIdx.x;
    const int m0 = blockIdx.y << 7;
    const int n0 = blockIdx.x << 7;
    const int ty = tid >> 4;              // 0..15
    const int tx = tid & 15;              // 0..15

    // A loader: thread -> (row = tid>>2 in 0..63 [+64 in pass 2], k-quad = (tid&3)*4)
    const int ar = tid >> 2;
    const int ak = (tid & 3) << 2;
    const float* Ap0 = A + (size_t)(m0 + ar) * K + ak;
    const float* Ap1 = A + (size_t)(m0 + ar + 64) * K + ak;
    // B loader: thread -> (row = tid>>5 in 0..7 [+8 pass 2], col-quad = (tid&31)*4)
    const int br = tid >> 5;
    const int bc = (tid & 31) << 2;
    const float* Bp0 = B + (size_t)br * N + n0 + bc;
    const float* Bp1 = B + (size_t)(br + 8) * N + n0 + bc;

    float acc[8][8];
#pragma unroll
    for (int i = 0; i < 8; i++)
#pragma unroll
        for (int j = 0; j < 8; j++) acc[i][j] = 0.f;

    for (int k0 = 0; k0 < K; k0 += 16) {
        float4 a0 = *(const float4*)(Ap0 + k0);
        float4 a1 = *(const float4*)(Ap1 + k0);
        float4 b0 = *(const float4*)(Bp0 + (size_t)k0 * N);
        float4 b1 = *(const float4*)(Bp1 + (size_t)k0 * N);
        __syncthreads();
        As[ak + 0][ar] = a0.x; As[ak + 1][ar] = a0.y;
        As[ak + 2][ar] = a0.z; As[ak + 3][ar] = a0.w;
        As[ak + 0][ar + 64] = a1.x; As[ak + 1][ar + 64] = a1.y;
        As[ak + 2][ar + 64] = a1.z; As[ak + 3][ar + 64] = a1.w;
        *(float4*)&Bs[br][bc]     = b0;
        *(float4*)&Bs[br + 8][bc] = b1;
        __syncthreads();
#pragma unroll
        for (int k = 0; k < 16; k++) {
            float4 x0 = *(const float4*)&As[k][ty << 2];
            float4 x1 = *(const float4*)&As[k][64 + (ty << 2)];
            float4 y0 = *(const float4*)&Bs[k][tx << 2];
            float4 y1 = *(const float4*)&Bs[k][64 + (tx << 2)];
            float xa[8] = {x0.x, x0.y, x0.z, x0.w, x1.x, x1.y, x1.z, x1.w};
            float yb[8] = {y0.x, y0.y, y0.z, y0.w, y1.x, y1.y, y1.z, y1.w};
#pragma unroll
            for (int i = 0; i < 8; i++)
#pragma unroll
                for (int j = 0; j < 8; j++) acc[i][j] += xa[i] * yb[j];
        }
    }

#pragma unroll
    for (int i = 0; i < 8; i++) {
        int row = m0 + ((i < 4) ? (ty * 4 + i) : (64 + ty * 4 + i - 4));
        float* Cp = C + (size_t)row * N + n0;
        *(float4*)(Cp + (tx << 2))      = make_float4(acc[i][0], acc[i][1], acc[i][2], acc[i][3]);
        *(float4*)(Cp + 64 + (tx << 2)) = make_float4(acc[i][4], acc[i][5], acc[i][6], acc[i][7]);
    }
}

// ============ 64x64x16 fp32 GEMM (for N not %128) ============
__global__ __launch_bounds__(256) void gemm64(
    const float* __restrict__ A, const float* __restrict__ B,
    float* __restrict__ C, int M, int N, int K)
{
    __shared__ float As[16][64];
    __shared__ float Bs[16][64];

    const int tid = threadIdx.x;
    const int m0 = blockIdx.y << 6;
    const int n0 = blockIdx.x << 6;
    const int ty = tid >> 4;
    const int tx = tid & 15;

    const int arow = tid >> 2;
    const int acol = (tid & 3) << 2;
    const int brow = tid >> 4;
    const int bcol = (tid & 15) << 2;

    const float* Ap = A + (size_t)(m0 + arow) * K + acol;
    const float* Bp = B + (size_t)brow * N + n0 + bcol;

    float acc[4][4];
#pragma unroll
    for (int i = 0; i < 4; i++)
#pragma unroll
        for (int j = 0; j < 4; j++) acc[i][j] = 0.f;

    for (int k0 = 0; k0 < K; k0 += 16) {
        float4 a4 = *(const float4*)(Ap + k0);
        float4 b4 = *(const float4*)(Bp + (size_t)k0 * N);
        __syncthreads();
        As[acol + 0][arow] = a4.x;
        As[acol + 1][arow] = a4.y;
        As[acol + 2][arow] = a4.z;
        As[acol + 3][arow] = a4.w;
        *(float4*)&Bs[brow][bcol] = b4;
        __syncthreads();
#pragma unroll
        for (int k = 0; k < 16; k++) {
            float4 av = *(const float4*)&As[k][ty << 2];
            float4 bv = *(const float4*)&Bs[k][tx << 2];
            acc[0][0] += av.x * bv.x; acc[0][1] += av.x * bv.y;
            acc[0][2] += av.x * bv.z; acc[0][3] += av.x * bv.w;
            acc[1][0] += av.y * bv.x; acc[1][1] += av.y * bv.y;
            acc[1][2] += av.y * bv.z; acc[1][3] += av.y * bv.w;
            acc[2][0] += av.z * bv.x; acc[2][1] += av.z * bv.y;
            acc[2][2] += av.z * bv.z; acc[2][3] += av.z * bv.w;
            acc[3][0] += av.w * bv.x; acc[3][1] += av.w * bv.y;
            acc[3][2] += av.w * bv.z; acc[3][3] += av.w * bv.w;
        }
    }

    float* Cp = C + (size_t)(m0 + (ty << 2)) * N + n0 + (tx << 2);
#pragma unroll
    for (int i = 0; i < 4; i++)
        *(float4*)(Cp + (size_t)i * N) = make_float4(acc[i][0], acc[i][1], acc[i][2], acc[i][3]);
}

// ---------------- row-wise rmsnorm (in place), 256 threads ----------------
__global__ __launch_bounds__(256) void rmsnorm_rows(
    float* __restrict__ x, const float* __restrict__ w, int len)
{
    __shared__ float sb[8];
    float* row = x + (size_t)blockIdx.x * len;
    float ss = 0.f;
    for (int i = threadIdx.x; i < len; i += 256) { float v = row[i]; ss += v * v; }
    ss = warp_sum(ss);
    if ((threadIdx.x & 31) == 0) sb[threadIdx.x >> 5] = ss;
    __syncthreads();
    float tot = 0.f;
#pragma unroll
    for (int i = 0; i < 8; i++) tot += sb[i];
    float sc = rsqrtf(tot / (float)len + EPSV);
    for (int i = threadIdx.x; i < len; i += 256) row[i] = row[i] * sc * w[i];
}

// ---------------- build q ----------------
__global__ __launch_bounds__(128) void q_build(
    const float* __restrict__ qn, const float* __restrict__ qr,
    const float* __restrict__ qhw,
    const float* __restrict__ fc, const float* __restrict__ fs,
    float* __restrict__ q)
{
    __shared__ float sb[4];
    const int token = blockIdx.y, h = blockIdx.x;
    const int t = token & (TSEQ - 1);
    const float* xn = qn + (size_t)token * NH * NND + h * NND;
    float v = xn[threadIdx.x];
    float ss = warp_sum(v * v);
    if ((threadIdx.x & 31) == 0) sb[threadIdx.x >> 5] = ss;
    __syncthreads();
    float tot = sb[0] + sb[1] + sb[2] + sb[3];
    float sc = rsqrtf(tot / (float)NND + EPSV);
    float* qo = q + ((size_t)token * NH + h) * DQK;
    qo[threadIdx.x] = v * sc * qhw[threadIdx.x];
    if (threadIdx.x < NRD / 2) {
        int i = threadIdx.x;
        const float* xr = qr + (size_t)token * NH * NRD + h * NRD;
        float a = xr[2 * i], b = xr[2 * i + 1];
        float c = fc[t * (NRD / 2) + i], s = fs[t * (NRD / 2) + i];
        qo[NND + 2 * i]     = a * c - b * s;
        qo[NND + 2 * i + 1] = a * s + b * c;
    }
}

// ---------------- kv post ----------------
__global__ __launch_bounds__(128) void kv_post(
    const float* __restrict__ kvraw, const float* __restrict__ kvw,
    const float* __restrict__ fc, const float* __restrict__ fs,
    float* __restrict__ ckv, float* __restrict__ kr)
{
    __shared__ float sb[4];
    const int token = blockIdx.x;
    const int t = token & (TSEQ - 1);
    const float* row = kvraw + (size_t)token * (NKVLR + NRD);
    float ss = 0.f;
    for (int i = threadIdx.x; i < NKVLR; i += 128) { float v = row[i]; ss += v * v; }
    ss = warp_sum(ss);
    if ((threadIdx.x & 31) == 0) sb[threadIdx.x >> 5] = ss;
    __syncthreads();
    float tot = sb[0] + sb[1] + sb[2] + sb[3];
    float sc = rsqrtf(tot / (float)NKVLR + EPSV);
    for (int i = threadIdx.x; i < NKVLR; i += 128)
        ckv[(size_t)token * NKVLR + i] = row[i] * sc * kvw[i];
    if (threadIdx.x < NRD / 2) {
        int i = threadIdx.x;
        float a = row[NKVLR + 2 * i], b = row[NKVLR + 2 * i + 1];
        float c = fc[t * (NRD / 2) + i], s = fs[t * (NRD / 2) + i];
        kr[(size_t)token * NRD + 2 * i]     = a * c - b * s;
        kr[(size_t)token * NRD + 2 * i + 1] = a * s + b * c;
    }
}

// ---------------- build k ----------------
__global__ __launch_bounds__(128) void k_build(
    const float* __restrict__ kv, const float* __restrict__ khw,
    const float* __restrict__ kr, float* __restrict__ k)
{
    __shared__ float sb[4];
    const int token = blockIdx.y, h = blockIdx.x;
    const float* kn = kv + ((size_t)token * NH + h) * (NND + NVD);
    float v = kn[threadIdx.x];
    float ss = warp_sum(v * v);
    if ((threadIdx.x & 31) == 0) sb[threadIdx.x >> 5] = ss;
    __syncthreads();
    float tot = sb[0] + sb[1] + sb[2] + sb[3];
    float sc = rsqrtf(tot / (float)NND + EPSV);
    float* ko = k + ((size_t)token * NH + h) * DQK;
    ko[threadIdx.x] = v * sc * khw[threadIdx.x];
    if (threadIdx.x < NRD) ko[NND + threadIdx.x] = kr[(size_t)token * NRD + threadIdx.x];
}

// ============ causal flash attention v2: 64q x 64k tiles, register microtiles ============
// grid: (TSEQ/64, B*H). block 256 = 16x16; thread owns 4 score rows x 4 cols,
// and 4 out rows x 8 out cols. Q/K staged transposed [d][tok] in d-chunks of 32.
// Dynamic smem layout (floats):
//   Qs[32][68] @ 0      Ks[32][68] @ 2176
//   Ps[64][68] @ 4352   Vs[64][132] @ 8704     total 17152 floats = 68608 B
#define ATTN_SMEM_BYTES (17152 * 4)

__global__ __launch_bounds__(256) void attn_kernel(
    const float* __restrict__ q, const float* __restrict__ k,
    const float* __restrict__ kv, float* __restrict__ ao)
{
    extern __shared__ float sm[];
    float* Qs = sm;            // [d][m] stride 68
    float* Ks = sm + 2176;     // [d][n] stride 68
    float* Ps = sm + 4352;     // [i][j] stride 68
    float* Vs = sm + 8704;     // [j][c] stride 132

    const int tid = threadIdx.x;
    const int ty = tid >> 4, tx = tid & 15;
    const int qt = (int)gridDim.x - 1 - (int)blockIdx.x;   // big tiles first
    const int bh = blockIdx.y;
    const int b = bh >> 4, h = bh & 15;
    const int qt0 = qt << 6;
    const int bT = b * TSEQ;
    const float SCALE = 0.07216878364870322f; // 1/sqrt(192)

    const float* qh = q  + ((size_t)(bT + qt0) * NH + h) * DQK;             // row stride 3072
    const float* vh = kv + ((size_t)bT * NH + h) * (NND + NVD) + NND;       // row stride 4096

    float rm[4], rl[4], acc[4][8];
#pragma unroll
    for (int i = 0; i < 4; i++) { rm[i] = -1e30f; rl[i] = 0.f; }
#pragma unroll
    for (int i = 0; i < 4; i++)
#pragma unroll
        for (int c = 0; c < 8; c++) acc[i][c] = 0.f;

    const int ldj = tid >> 3;     // 0..31 (transpose loader row)
    const int ldd = tid & 7;      // 0..7  (d-quad)

    for (int kt = 0; kt <= qt; kt++) {
        const int kt0 = kt << 6;
        const float* kh = k + ((size_t)(bT + kt0) * NH + h) * DQK;

        // ---- load V tile 64x128 (coalesced, conflict-free stores) ----
#pragma unroll
        for (int p = 0; p < 8; p++) {
            int e = p * 256 + tid;
            int j = e >> 5, cg = (e & 31) << 2;
            float4 v4 = *(const float4*)(vh + (size_t)(kt0 + j) * (NH * (NND + NVD)) + cg);
            *(float4*)&Vs[j * 132 + cg] = v4;
        }

        // ---- scores: 6 d-chunks of 32 ----
        float sreg[4][4];
#pragma unroll
        for (int i = 0; i < 4; i++)
#pragma unroll
            for (int j = 0; j < 4; j++) sreg[i][j] = 0.f;

        for (int dc = 0; dc < 6; dc++) {
            const int doff = dc * 32 + ldd * 4;
            __syncthreads();
#pragma unroll
            for (int p = 0; p < 2; p++) {
                int jr = (p << 5) + ldj;
                float4 a = *(const float4*)(qh + (size_t)jr * (NH * DQK) + doff);
                float* dq = &Qs[(ldd * 4) * 68 + jr];
                dq[0] = a.x; dq[68] = a.y; dq[136] = a.z; dq[204] = a.w;
                float4 bb = *(const float4*)(kh + (size_t)jr * (NH * DQK) + doff);
                float* dk = &Ks[(ldd * 4) * 68 + jr];
                dk[0] = bb.x; dk[68] = bb.y; dk[136] = bb.z; dk[204] = bb.w;
            }
            __syncthreads();
#pragma unroll
            for (int dd = 0; dd < 32; dd++) {
                float4 qv = *(const float4*)&Qs[dd * 68 + (ty << 2)];
                float4 kv4 = *(const float4*)&Ks[dd * 68 + (tx << 2)];
                float qa[4] = {qv.x, qv.y, qv.z, qv.w};
                float kb[4] = {kv4.x, kv4.y, kv4.z, kv4.w};
#pragma unroll
                for (int i = 0; i < 4; i++)
#pragma unroll
                    for (int j = 0; j < 4; j++) sreg[i][j] += qa[i] * kb[j];
            }
        }

        // ---- scale + causal mask (diag tile only) ----
#pragma unroll
        for (int i = 0; i < 4; i++)
#pragma unroll
            for (int j = 0; j < 4; j++) sreg[i][j] *= SCALE;
        if (kt == qt) {
#pragma unroll
            for (int i = 0; i < 4; i++) {
                int ir = ty * 4 + i;
#pragma unroll
                for (int j = 0; j < 4; j++)
                    if (tx * 4 + j > ir) sreg[i][j] = -1e30f;
            }
        }

        // ---- online softmax (row groups = 16 consecutive lanes) ----
#pragma unroll
        for (int i = 0; i < 4; i++) {
            float mt = fmaxf(fmaxf(sreg[i][0], sreg[i][1]), fmaxf(sreg[i][2], sreg[i][3]));
            mt = fmaxf(mt, __shfl_xor_sync(0xffffffffu, mt, 1));
            mt = fmaxf(mt, __shfl_xor_sync(0xffffffffu, mt, 2));
            mt = fmaxf(mt, __shfl_xor_sync(0xffffffffu, mt, 4));
            mt = fmaxf(mt, __shfl_xor_sync(0xffffffffu, mt, 8));
            float mn = fmaxf(rm[i], mt);
            float corr = __expf(rm[i] - mn);
            float ps = 0.f;
#pragma unroll
            for (int j = 0; j < 4; j++) {
                float e = __expf(sreg[i][j] - mn);
                sreg[i][j] = e;
                ps += e;
            }
            ps += __shfl_xor_sync(0xffffffffu, ps, 1);
            ps += __shfl_xor_sync(0xffffffffu, ps, 2);
            ps += __shfl_xor_sync(0xffffffffu, ps, 4);
            ps += __shfl_xor_sync(0xffffffffu, ps, 8);
            rl[i] = rl[i] * corr + ps;
            rm[i] = mn;
#pragma unroll
            for (int c = 0; c < 8; c++) acc[i][c] *= corr;
            *(float4*)&Ps[(ty * 4 + i) * 68 + (tx << 2)] =
                make_float4(sreg[i][0], sreg[i][1], sreg[i][2], sreg[i][3]);
        }
        __syncthreads();

        // ---- PV: 64 keys x (4 rows x 8 cols) ----
#pragma unroll 4
        for (int j = 0; j < 64; j++) {
            float p0 = Ps[(ty * 4 + 0) * 68 + j];
            float p1 = Ps[(ty * 4 + 1) * 68 + j];
            float p2 = Ps[(ty * 4 + 2) * 68 + j];
            float p3 = Ps[(ty * 4 + 3) * 68 + j];
            float4 v0 = *(const float4*)&Vs[j * 132 + (tx << 2)];
            float4 v1 = *(const float4*)&Vs[j * 132 + 64 + (tx << 2)];
            float vb[8] = {v0.x, v0.y, v0.z, v0.w, v1.x, v1.y, v1.z, v1.w};
#pragma unroll
            for (int c = 0; c < 8; c++) {
                acc[0][c] += p0 * vb[c];
                acc[1][c] += p1 * vb[c];
                acc[2][c] += p2 * vb[c];
                acc[3][c] += p3 * vb[c];
            }
        }
        __syncthreads();
    }

    // ---- write output ----
#pragma unroll
    for (int i = 0; i < 4; i++) {
        float inv = 1.f / rl[i];
        int tok = qt0 + ty * 4 + i;
        float* op = ao + ((size_t)(bT + tok) * NH + h) * NVD;
        *(float4*)(op + (tx << 2))      = make_float4(acc[i][0] * inv, acc[i][1] * inv,
                                                      acc[i][2] * inv, acc[i][3] * inv);
        *(float4*)(op + 64 + (tx << 2)) = make_float4(acc[i][4] * inv, acc[i][5] * inv,
                                                      acc[i][6] * inv, acc[i][7] * inv);
    }
}

// ---------------- launch ----------------
extern "C" void kernel_launch(void* const* d_in, const int* in_sizes, int n_in,
                              void* d_out, int out_size)
{
    const float* x    = (const float*)d_in[0];
    const float* fc   = (const float*)d_in[1];
    const float* fs   = (const float*)d_in[2];
    const float* qdw  = (const float*)d_in[3];
    const float* qnw  = (const float*)d_in[4];
    const float* qunw = (const float*)d_in[5];
    const float* qurw = (const float*)d_in[6];
    const float* kdw  = (const float*)d_in[7];
    const float* kvnw = (const float*)d_in[8];
    const float* kuw  = (const float*)d_in[9];
    const float* qhw  = (const float*)d_in[10];
    const float* khw  = (const float*)d_in[11];
    const float* wow  = (const float*)d_in[12];
    float* out = (float*)d_out;

    float *p_cq, *p_qn, *p_qr, *p_q, *p_kvraw, *p_ckv, *p_kr, *p_kv, *p_k, *p_ao;
    cudaGetSymbolAddress((void**)&p_cq,    g_cq);
    cudaGetSymbolAddress((void**)&p_qn,    g_qn);
    cudaGetSymbolAddress((void**)&p_qr,    g_qr);
    cudaGetSymbolAddress((void**)&p_q,     g_q);
    cudaGetSymbolAddress((void**)&p_kvraw, g_kvraw);
    cudaGetSymbolAddress((void**)&p_ckv,   g_ckv);
    cudaGetSymbolAddress((void**)&p_kr,    g_kr);
    cudaGetSymbolAddress((void**)&p_kv,    g_kv);
    cudaGetSymbolAddress((void**)&p_k,     g_k);
    cudaGetSymbolAddress((void**)&p_ao,    g_ao);

    cudaFuncSetAttribute(attn_kernel, cudaFuncAttributeMaxDynamicSharedMemorySize,
                         ATTN_SMEM_BYTES);

    // c_q = x @ q_down_w ; rmsnorm
    gemm128<<<dim3(NQLR / 128, NTOK / 128), 256>>>(x, qdw, p_cq, NTOK, NQLR, NDIM);
    rmsnorm_rows<<<NTOK, 256>>>(p_cq, qnw, NQLR);

    // q projections
    gemm128<<<dim3((NH * NND) / 128, NTOK / 128), 256>>>(p_cq, qunw, p_qn, NTOK, NH * NND, NQLR);
    gemm128<<<dim3((NH * NRD) / 128, NTOK / 128), 256>>>(p_cq, qurw, p_qr, NTOK, NH * NRD, NQLR);

    // kv down (N=576 not %128 -> gemm64)
    gemm64<<<dim3((NKVLR + NRD) / 64, NTOK / 64), 256>>>(x, kdw, p_kvraw, NTOK, NKVLR + NRD, NDIM);

    // epilogues
    q_build<<<dim3(NH, NTOK), 128>>>(p_qn, p_qr, qhw, fc, fs, p_q);
    kv_post<<<NTOK, 128>>>(p_kvraw, kvnw, fc, fs, p_ckv, p_kr);

    // kv up + k build
    gemm128<<<dim3((NH * (NND + NVD)) / 128, NTOK / 128), 256>>>(p_ckv, kuw, p_kv, NTOK, NH * (NND + NVD), NKVLR);
    k_build<<<dim3(NH, NTOK), 128>>>(p_kv, khw, p_kr, p_k);

    // attention
    attn_kernel<<<dim3(TSEQ / 64, NB * NH), 256, ATTN_SMEM_BYTES>>>(p_q, p_k, p_kv, p_ao);

    // output projection
    gemm128<<<dim3(NDIM / 128, NTOK / 128), 256>>>(p_ao, wow, out, NTOK, NDIM, NH * NVD);
}

// round 8
// speedup vs baseline: 3.6605x; 1.4157x over previous
#include <cuda_runtime.h>
#include <math.h>
#include <stdint.h>

// ---------------- problem constants ----------------
#define NB      2
#define TSEQ    2048
#define NDIM    2048
#define NH      16
#define NQLR    1536
#define NKVLR   512
#define NRD     64
#define NND     128
#define NVD     128
#define NTOK    (NB * TSEQ)        // 4096
#define DQK     (NND + NRD)        // 192
#define EPSV    1e-6f

// ---------------- scratch (no allocations allowed) ----------------
__device__ float g_cq   [(size_t)NTOK * NQLR];
__device__ float g_qn   [(size_t)NTOK * NH * NND];
__device__ float g_qr   [(size_t)NTOK * NH * NRD];
__device__ float g_q    [(size_t)NTOK * NH * DQK];
__device__ float g_kvraw[(size_t)NTOK * (NKVLR + NRD)];
__device__ float g_ckv  [(size_t)NTOK * NKVLR];
__device__ float g_kr   [(size_t)NTOK * NRD];
__device__ float g_kv   [(size_t)NTOK * NH * (NND + NVD)];
__device__ float g_k    [(size_t)NTOK * NH * DQK];
__device__ float g_ao   [(size_t)NTOK * NH * NVD];

// ---------------- helpers ----------------
__device__ __forceinline__ float warp_sum(float v) {
#pragma unroll
    for (int o = 16; o; o >>= 1) v += __shfl_xor_sync(0xffffffffu, v, o);
    return v;
}

__device__ __forceinline__ uint32_t f2tf32(float f) {
    uint32_t r;
    asm("cvt.rna.tf32.f32 %0, %1;" : "=r"(r) : "f"(f));
    return r;
}

__device__ __forceinline__ void mma_tf32(
    float& c0, float& c1, float& c2, float& c3,
    uint32_t a0, uint32_t a1, uint32_t a2, uint32_t a3,
    uint32_t b0, uint32_t b1)
{
    asm volatile(
        "mma.sync.aligned.m16n8k8.row.col.f32.tf32.tf32.f32 "
        "{%0,%1,%2,%3}, {%4,%5,%6,%7}, {%8,%9}, {%0,%1,%2,%3};"
        : "+f"(c0), "+f"(c1), "+f"(c2), "+f"(c3)
        : "r"(a0), "r"(a1), "r"(a2), "r"(a3), "r"(b0), "r"(b1));
}

// ============ tf32 tensor-core GEMM: 128x128x32 tile, 8 warps, 64x32/warp ============
// C[M,N] = A[M,K] @ B[K,N], row-major. Requires M%128==0, N%128==0, K%32==0.
__global__ __launch_bounds__(256, 1) void gemm_tf32(
    const float* __restrict__ A, const float* __restrict__ B,
    float* __restrict__ C, int M, int N, int K)
{
    __shared__ uint32_t As[128][36];   // [m][k], pad->bank = m*4+k (conflict-free frags)
    __shared__ uint32_t Bs[32][136];   // [k][n], pad->bank = k*8+n (conflict-free frags)

    const int tid  = threadIdx.x;
    const int wid  = tid >> 5;
    const int lane = tid & 31;
    const int g    = lane >> 2;   // 0..7
    const int tg   = lane & 3;    // 0..3
    const int warp_m = (wid >> 2) * 64;   // 0 or 64
    const int warp_n = (wid & 3) * 32;    // 0,32,64,96

    const int m0 = blockIdx.y << 7;
    const int n0 = blockIdx.x << 7;

    // loaders
    const int ar = tid >> 3;              // 0..31 (A row within pass)
    const int akq = (tid & 7) << 2;       // k-quad 0..28
    const int br = tid >> 5;              // 0..7  (B k-row within pass)
    const int bc = (tid & 31) << 2;       // n-quad 0..124

    float acc[4][4][4];
#pragma unroll
    for (int mt = 0; mt < 4; mt++)
#pragma unroll
        for (int nt = 0; nt < 4; nt++)
#pragma unroll
            for (int c = 0; c < 4; c++) acc[mt][nt][c] = 0.f;

    for (int k0 = 0; k0 < K; k0 += 32) {
        float4 av[4], bv[4];
#pragma unroll
        for (int p = 0; p < 4; p++) {
            av[p] = *(const float4*)(A + (size_t)(m0 + ar + p * 32) * K + k0 + akq);
            bv[p] = *(const float4*)(B + (size_t)(k0 + br + p * 8) * N + n0 + bc);
        }
        __syncthreads();
#pragma unroll
        for (int p = 0; p < 4; p++) {
            uint32_t* da = &As[ar + p * 32][akq];
            da[0] = f2tf32(av[p].x); da[1] = f2tf32(av[p].y);
            da[2] = f2tf32(av[p].z); da[3] = f2tf32(av[p].w);
            uint32_t* db = &Bs[br + p * 8][bc];
            db[0] = f2tf32(bv[p].x); db[1] = f2tf32(bv[p].y);
            db[2] = f2tf32(bv[p].z); db[3] = f2tf32(bv[p].w);
        }
        __syncthreads();

#pragma unroll
        for (int k8 = 0; k8 < 4; k8++) {
            const int kk = k8 * 8;
            uint32_t afr[4][4], bfr[4][2];
#pragma unroll
            for (int mt = 0; mt < 4; mt++) {
                const int m = warp_m + mt * 16;
                afr[mt][0] = As[m + g][kk + tg];
                afr[mt][1] = As[m + g + 8][kk + tg];
                afr[mt][2] = As[m + g][kk + tg + 4];
                afr[mt][3] = As[m + g + 8][kk + tg + 4];
            }
#pragma unroll
            for (int nt = 0; nt < 4; nt++) {
                const int n = warp_n + nt * 8;
                bfr[nt][0] = Bs[kk + tg][n + g];
                bfr[nt][1] = Bs[kk + tg + 4][n + g];
            }
#pragma unroll
            for (int mt = 0; mt < 4; mt++)
#pragma unroll
                for (int nt = 0; nt < 4; nt++)
                    mma_tf32(acc[mt][nt][0], acc[mt][nt][1], acc[mt][nt][2], acc[mt][nt][3],
                             afr[mt][0], afr[mt][1], afr[mt][2], afr[mt][3],
                             bfr[nt][0], bfr[nt][1]);
        }
    }

    // epilogue: c0,c1 -> (row g, col tg*2 / +1); c2,c3 -> row g+8
#pragma unroll
    for (int mt = 0; mt < 4; mt++) {
        const int row = m0 + warp_m + mt * 16 + g;
#pragma unroll
        for (int nt = 0; nt < 4; nt++) {
            const int col = n0 + warp_n + nt * 8 + tg * 2;
            *(float2*)(C + (size_t)row * N + col)       = make_float2(acc[mt][nt][0], acc[mt][nt][1]);
            *(float2*)(C + (size_t)(row + 8) * N + col) = make_float2(acc[mt][nt][2], acc[mt][nt][3]);
        }
    }
}

// ============ 64x64x16 fp32 GEMM (for N not %128: kv_down) ============
__global__ __launch_bounds__(256) void gemm64(
    const float* __restrict__ A, const float* __restrict__ B,
    float* __restrict__ C, int M, int N, int K)
{
    __shared__ float As[16][64];
    __shared__ float Bs[16][64];

    const int tid = threadIdx.x;
    const int m0 = blockIdx.y << 6;
    const int n0 = blockIdx.x << 6;
    const int ty = tid >> 4;
    const int tx = tid & 15;

    const int arow = tid >> 2;
    const int acol = (tid & 3) << 2;
    const int brow = tid >> 4;
    const int bcol = (tid & 15) << 2;

    const float* Ap = A + (size_t)(m0 + arow) * K + acol;
    const float* Bp = B + (size_t)brow * N + n0 + bcol;

    float acc[4][4];
#pragma unroll
    for (int i = 0; i < 4; i++)
#pragma unroll
        for (int j = 0; j < 4; j++) acc[i][j] = 0.f;

    for (int k0 = 0; k0 < K; k0 += 16) {
        float4 a4 = *(const float4*)(Ap + k0);
        float4 b4 = *(const float4*)(Bp + (size_t)k0 * N);
        __syncthreads();
        As[acol + 0][arow] = a4.x;
        As[acol + 1][arow] = a4.y;
        As[acol + 2][arow] = a4.z;
        As[acol + 3][arow] = a4.w;
        *(float4*)&Bs[brow][bcol] = b4;
        __syncthreads();
#pragma unroll
        for (int k = 0; k < 16; k++) {
            float4 av = *(const float4*)&As[k][ty << 2];
            float4 bv = *(const float4*)&Bs[k][tx << 2];
            acc[0][0] += av.x * bv.x; acc[0][1] += av.x * bv.y;
            acc[0][2] += av.x * bv.z; acc[0][3] += av.x * bv.w;
            acc[1][0] += av.y * bv.x; acc[1][1] += av.y * bv.y;
            acc[1][2] += av.y * bv.z; acc[1][3] += av.y * bv.w;
            acc[2][0] += av.z * bv.x; acc[2][1] += av.z * bv.y;
            acc[2][2] += av.z * bv.z; acc[2][3] += av.z * bv.w;
            acc[3][0] += av.w * bv.x; acc[3][1] += av.w * bv.y;
            acc[3][2] += av.w * bv.z; acc[3][3] += av.w * bv.w;
        }
    }

    float* Cp = C + (size_t)(m0 + (ty << 2)) * N + n0 + (tx << 2);
#pragma unroll
    for (int i = 0; i < 4; i++)
        *(float4*)(Cp + (size_t)i * N) = make_float4(acc[i][0], acc[i][1], acc[i][2], acc[i][3]);
}

// ---------------- row-wise rmsnorm (in place), 256 threads ----------------
__global__ __launch_bounds__(256) void rmsnorm_rows(
    float* __restrict__ x, const float* __restrict__ w, int len)
{
    __shared__ float sb[8];
    float* row = x + (size_t)blockIdx.x * len;
    float ss = 0.f;
    for (int i = threadIdx.x; i < len; i += 256) { float v = row[i]; ss += v * v; }
    ss = warp_sum(ss);
    if ((threadIdx.x & 31) == 0) sb[threadIdx.x >> 5] = ss;
    __syncthreads();
    float tot = 0.f;
#pragma unroll
    for (int i = 0; i < 8; i++) tot += sb[i];
    float sc = rsqrtf(tot / (float)len + EPSV);
    for (int i = threadIdx.x; i < len; i += 256) row[i] = row[i] * sc * w[i];
}

// ---------------- build q ----------------
__global__ __launch_bounds__(128) void q_build(
    const float* __restrict__ qn, const float* __restrict__ qr,
    const float* __restrict__ qhw,
    const float* __restrict__ fc, const float* __restrict__ fs,
    float* __restrict__ q)
{
    __shared__ float sb[4];
    const int token = blockIdx.y, h = blockIdx.x;
    const int t = token & (TSEQ - 1);
    const float* xn = qn + (size_t)token * NH * NND + h * NND;
    float v = xn[threadIdx.x];
    float ss = warp_sum(v * v);
    if ((threadIdx.x & 31) == 0) sb[threadIdx.x >> 5] = ss;
    __syncthreads();
    float tot = sb[0] + sb[1] + sb[2] + sb[3];
    float sc = rsqrtf(tot / (float)NND + EPSV);
    float* qo = q + ((size_t)token * NH + h) * DQK;
    qo[threadIdx.x] = v * sc * qhw[threadIdx.x];
    if (threadIdx.x < NRD / 2) {
        int i = threadIdx.x;
        const float* xr = qr + (size_t)token * NH * NRD + h * NRD;
        float a = xr[2 * i], b = xr[2 * i + 1];
        float c = fc[t * (NRD / 2) + i], s = fs[t * (NRD / 2) + i];
        qo[NND + 2 * i]     = a * c - b * s;
        qo[NND + 2 * i + 1] = a * s + b * c;
    }
}

// ---------------- kv post ----------------
__global__ __launch_bounds__(128) void kv_post(
    const float* __restrict__ kvraw, const float* __restrict__ kvw,
    const float* __restrict__ fc, const float* __restrict__ fs,
    float* __restrict__ ckv, float* __restrict__ kr)
{
    __shared__ float sb[4];
    const int token = blockIdx.x;
    const int t = token & (TSEQ - 1);
    const float* row = kvraw + (size_t)token * (NKVLR + NRD);
    float ss = 0.f;
    for (int i = threadIdx.x; i < NKVLR; i += 128) { float v = row[i]; ss += v * v; }
    ss = warp_sum(ss);
    if ((threadIdx.x & 31) == 0) sb[threadIdx.x >> 5] = ss;
    __syncthreads();
    float tot = sb[0] + sb[1] + sb[2] + sb[3];
    float sc = rsqrtf(tot / (float)NKVLR + EPSV);
    for (int i = threadIdx.x; i < NKVLR; i += 128)
        ckv[(size_t)token * NKVLR + i] = row[i] * sc * kvw[i];
    if (threadIdx.x < NRD / 2) {
        int i = threadIdx.x;
        float a = row[NKVLR + 2 * i], b = row[NKVLR + 2 * i + 1];
        float c = fc[t * (NRD / 2) + i], s = fs[t * (NRD / 2) + i];
        kr[(size_t)token * NRD + 2 * i]     = a * c - b * s;
        kr[(size_t)token * NRD + 2 * i + 1] = a * s + b * c;
    }
}

// ---------------- build k ----------------
__global__ __launch_bounds__(128) void k_build(
    const float* __restrict__ kv, const float* __restrict__ khw,
    const float* __restrict__ kr, float* __restrict__ k)
{
    __shared__ float sb[4];
    const int token = blockIdx.y, h = blockIdx.x;
    const float* kn = kv + ((size_t)token * NH + h) * (NND + NVD);
    float v = kn[threadIdx.x];
    float ss = warp_sum(v * v);
    if ((threadIdx.x & 31) == 0) sb[threadIdx.x >> 5] = ss;
    __syncthreads();
    float tot = sb[0] + sb[1] + sb[2] + sb[3];
    float sc = rsqrtf(tot / (float)NND + EPSV);
    float* ko = k + ((size_t)token * NH + h) * DQK;
    ko[threadIdx.x] = v * sc * khw[threadIdx.x];
    if (threadIdx.x < NRD) ko[NND + threadIdx.x] = kr[(size_t)token * NRD + threadIdx.x];
}

// ============ causal flash attention: 64q x 64k tiles, register microtiles ============
#define ATTN_SMEM_BYTES (17152 * 4)

__global__ __launch_bounds__(256) void attn_kernel(
    const float* __restrict__ q, const float* __restrict__ k,
    const float* __restrict__ kv, float* __restrict__ ao)
{
    extern __shared__ float sm[];
    float* Qs = sm;            // [d][m] stride 68
    float* Ks = sm + 2176;     // [d][n] stride 68
    float* Ps = sm + 4352;     // [i][j] stride 68
    float* Vs = sm + 8704;     // [j][c] stride 132

    const int tid = threadIdx.x;
    const int ty = tid >> 4, tx = tid & 15;
    const int qt = (int)gridDim.x - 1 - (int)blockIdx.x;
    const int bh = blockIdx.y;
    const int b = bh >> 4, h = bh & 15;
    const int qt0 = qt << 6;
    const int bT = b * TSEQ;
    const float SCALE = 0.07216878364870322f;

    const float* qh = q  + ((size_t)(bT + qt0) * NH + h) * DQK;
    const float* vh = kv + ((size_t)bT * NH + h) * (NND + NVD) + NND;

    float rm[4], rl[4], acc[4][8];
#pragma unroll
    for (int i = 0; i < 4; i++) { rm[i] = -1e30f; rl[i] = 0.f; }
#pragma unroll
    for (int i = 0; i < 4; i++)
#pragma unroll
        for (int c = 0; c < 8; c++) acc[i][c] = 0.f;

    const int ldj = tid >> 3;
    const int ldd = tid & 7;

    for (int kt = 0; kt <= qt; kt++) {
        const int kt0 = kt << 6;
        const float* kh = k + ((size_t)(bT + kt0) * NH + h) * DQK;

#pragma unroll
        for (int p = 0; p < 8; p++) {
            int e = p * 256 + tid;
            int j = e >> 5, cg = (e & 31) << 2;
            float4 v4 = *(const float4*)(vh + (size_t)(kt0 + j) * (NH * (NND + NVD)) + cg);
            *(float4*)&Vs[j * 132 + cg] = v4;
        }

        float sreg[4][4];
#pragma unroll
        for (int i = 0; i < 4; i++)
#pragma unroll
            for (int j = 0; j < 4; j++) sreg[i][j] = 0.f;

        for (int dc = 0; dc < 6; dc++) {
            const int doff = dc * 32 + ldd * 4;
            __syncthreads();
#pragma unroll
            for (int p = 0; p < 2; p++) {
                int jr = (p << 5) + ldj;
                float4 a = *(const float4*)(qh + (size_t)jr * (NH * DQK) + doff);
                float* dq = &Qs[(ldd * 4) * 68 + jr];
                dq[0] = a.x; dq[68] = a.y; dq[136] = a.z; dq[204] = a.w;
                float4 bb = *(const float4*)(kh + (size_t)jr * (NH * DQK) + doff);
                float* dk = &Ks[(ldd * 4) * 68 + jr];
                dk[0] = bb.x; dk[68] = bb.y; dk[136] = bb.z; dk[204] = bb.w;
            }
            __syncthreads();
#pragma unroll
            for (int dd = 0; dd < 32; dd++) {
                float4 qv = *(const float4*)&Qs[dd * 68 + (ty << 2)];
                float4 kv4 = *(const float4*)&Ks[dd * 68 + (tx << 2)];
                float qa[4] = {qv.x, qv.y, qv.z, qv.w};
                float kb[4] = {kv4.x, kv4.y, kv4.z, kv4.w};
#pragma unroll
                for (int i = 0; i < 4; i++)
#pragma unroll
                    for (int j = 0; j < 4; j++) sreg[i][j] += qa[i] * kb[j];
            }
        }

#pragma unroll
        for (int i = 0; i < 4; i++)
#pragma unroll
            for (int j = 0; j < 4; j++) sreg[i][j] *= SCALE;
        if (kt == qt) {
#pragma unroll
            for (int i = 0; i < 4; i++) {
                int ir = ty * 4 + i;
#pragma unroll
                for (int j = 0; j < 4; j++)
                    if (tx * 4 + j > ir) sreg[i][j] = -1e30f;
            }
        }

#pragma unroll
        for (int i = 0; i < 4; i++) {
            float mt = fmaxf(fmaxf(sreg[i][0], sreg[i][1]), fmaxf(sreg[i][2], sreg[i][3]));
            mt = fmaxf(mt, __shfl_xor_sync(0xffffffffu, mt, 1));
            mt = fmaxf(mt, __shfl_xor_sync(0xffffffffu, mt, 2));
            mt = fmaxf(mt, __shfl_xor_sync(0xffffffffu, mt, 4));
            mt = fmaxf(mt, __shfl_xor_sync(0xffffffffu, mt, 8));
            float mn = fmaxf(rm[i], mt);
            float corr = __expf(rm[i] - mn);
            float ps = 0.f;
#pragma unroll
            for (int j = 0; j < 4; j++) {
                float e = __expf(sreg[i][j] - mn);
                sreg[i][j] = e;
                ps += e;
            }
            ps += __shfl_xor_sync(0xffffffffu, ps, 1);
            ps += __shfl_xor_sync(0xffffffffu, ps, 2);
            ps += __shfl_xor_sync(0xffffffffu, ps, 4);
            ps += __shfl_xor_sync(0xffffffffu, ps, 8);
            rl[i] = rl[i] * corr + ps;
            rm[i] = mn;
#pragma unroll
            for (int c = 0; c < 8; c++) acc[i][c] *= corr;
            *(float4*)&Ps[(ty * 4 + i) * 68 + (tx << 2)] =
                make_float4(sreg[i][0], sreg[i][1], sreg[i][2], sreg[i][3]);
        }
        __syncthreads();

#pragma unroll 4
        for (int j = 0; j < 64; j++) {
            float p0 = Ps[(ty * 4 + 0) * 68 + j];
            float p1 = Ps[(ty * 4 + 1) * 68 + j];
            float p2 = Ps[(ty * 4 + 2) * 68 + j];
            float p3 = Ps[(ty * 4 + 3) * 68 + j];
            float4 v0 = *(const float4*)&Vs[j * 132 + (tx << 2)];
            float4 v1 = *(const float4*)&Vs[j * 132 + 64 + (tx << 2)];
            float vb[8] = {v0.x, v0.y, v0.z, v0.w, v1.x, v1.y, v1.z, v1.w};
#pragma unroll
            for (int c = 0; c < 8; c++) {
                acc[0][c] += p0 * vb[c];
                acc[1][c] += p1 * vb[c];
                acc[2][c] += p2 * vb[c];
                acc[3][c] += p3 * vb[c];
            }
        }
        __syncthreads();
    }

#pragma unroll
    for (int i = 0; i < 4; i++) {
        float inv = 1.f / rl[i];
        int tok = qt0 + ty * 4 + i;
        float* op = ao + ((size_t)(bT + tok) * NH + h) * NVD;
        *(float4*)(op + (tx << 2))      = make_float4(acc[i][0] * inv, acc[i][1] * inv,
                                                      acc[i][2] * inv, acc[i][3] * inv);
        *(float4*)(op + 64 + (tx << 2)) = make_float4(acc[i][4] * inv, acc[i][5] * inv,
                                                      acc[i][6] * inv, acc[i][7] * inv);
    }
}

// ---------------- launch ----------------
extern "C" void kernel_launch(void* const* d_in, const int* in_sizes, int n_in,
                              void* d_out, int out_size)
{
    const float* x    = (const float*)d_in[0];
    const float* fc   = (const float*)d_in[1];
    const float* fs   = (const float*)d_in[2];
    const float* qdw  = (const float*)d_in[3];
    const float* qnw  = (const float*)d_in[4];
    const float* qunw = (const float*)d_in[5];
    const float* qurw = (const float*)d_in[6];
    const float* kdw  = (const float*)d_in[7];
    const float* kvnw = (const float*)d_in[8];
    const float* kuw  = (const float*)d_in[9];
    const float* qhw  = (const float*)d_in[10];
    const float* khw  = (const float*)d_in[11];
    const float* wow  = (const float*)d_in[12];
    float* out = (float*)d_out;

    float *p_cq, *p_qn, *p_qr, *p_q, *p_kvraw, *p_ckv, *p_kr, *p_kv, *p_k, *p_ao;
    cudaGetSymbolAddress((void**)&p_cq,    g_cq);
    cudaGetSymbolAddress((void**)&p_qn,    g_qn);
    cudaGetSymbolAddress((void**)&p_qr,    g_qr);
    cudaGetSymbolAddress((void**)&p_q,     g_q);
    cudaGetSymbolAddress((void**)&p_kvraw, g_kvraw);
    cudaGetSymbolAddress((void**)&p_ckv,   g_ckv);
    cudaGetSymbolAddress((void**)&p_kr,    g_kr);
    cudaGetSymbolAddress((void**)&p_kv,    g_kv);
    cudaGetSymbolAddress((void**)&p_k,     g_k);
    cudaGetSymbolAddress((void**)&p_ao,    g_ao);

    cudaFuncSetAttribute(attn_kernel, cudaFuncAttributeMaxDynamicSharedMemorySize,
                         ATTN_SMEM_BYTES);

    // c_q = x @ q_down_w ; rmsnorm
    gemm_tf32<<<dim3(NQLR / 128, NTOK / 128), 256>>>(x, qdw, p_cq, NTOK, NQLR, NDIM);
    rmsnorm_rows<<<NTOK, 256>>>(p_cq, qnw, NQLR);

    // q projections
    gemm_tf32<<<dim3((NH * NND) / 128, NTOK / 128), 256>>>(p_cq, qunw, p_qn, NTOK, NH * NND, NQLR);
    gemm_tf32<<<dim3((NH * NRD) / 128, NTOK / 128), 256>>>(p_cq, qurw, p_qr, NTOK, NH * NRD, NQLR);

    // kv down (N=576 not %128 -> fp32 gemm64)
    gemm64<<<dim3((NKVLR + NRD) / 64, NTOK / 64), 256>>>(x, kdw, p_kvraw, NTOK, NKVLR + NRD, NDIM);

    // epilogues
    q_build<<<dim3(NH, NTOK), 128>>>(p_qn, p_qr, qhw, fc, fs, p_q);
    kv_post<<<NTOK, 128>>>(p_kvraw, kvnw, fc, fs, p_ckv, p_kr);

    // kv up + k build
    gemm_tf32<<<dim3((NH * (NND + NVD)) / 128, NTOK / 128), 256>>>(p_ckv, kuw, p_kv, NTOK, NH * (NND + NVD), NKVLR);
    k_build<<<dim3(NH, NTOK), 128>>>(p_kv, khw, p_kr, p_k);

    // attention
    attn_kernel<<<dim3(TSEQ / 64, NB * NH), 256, ATTN_SMEM_BYTES>>>(p_q, p_k, p_kv, p_ao);

    // output projection
    gemm_tf32<<<dim3(NDIM / 128, NTOK / 128), 256>>>(p_ao, wow, out, NTOK, NDIM, NH * NVD);
}

// round 9
// speedup vs baseline: 3.8327x; 1.0471x over previous
#include <cuda_runtime.h>
#include <math.h>
#include <stdint.h>

// ---------------- problem constants ----------------
#define NB      2
#define TSEQ    2048
#define NDIM    2048
#define NH      16
#define NQLR    1536
#define NKVLR   512
#define NRD     64
#define NND     128
#define NVD     128
#define NTOK    (NB * TSEQ)        // 4096
#define DQK     (NND + NRD)        // 192
#define EPSV    1e-6f

// ---------------- scratch (no allocations allowed) ----------------
__device__ float g_cq   [(size_t)NTOK * NQLR];
__device__ float g_qn   [(size_t)NTOK * NH * NND];
__device__ float g_qr   [(size_t)NTOK * NH * NRD];
__device__ float g_q    [(size_t)NTOK * NH * DQK];
__device__ float g_kvraw[(size_t)NTOK * (NKVLR + NRD)];
__device__ float g_ckv  [(size_t)NTOK * NKVLR];
__device__ float g_kr   [(size_t)NTOK * NRD];
__device__ float g_kv   [(size_t)NTOK * NH * (NND + NVD)];
__device__ float g_k    [(size_t)NTOK * NH * DQK];
__device__ float g_ao   [(size_t)NTOK * NH * NVD];

// ---------------- helpers ----------------
__device__ __forceinline__ float warp_sum(float v) {
#pragma unroll
    for (int o = 16; o; o >>= 1) v += __shfl_xor_sync(0xffffffffu, v, o);
    return v;
}

__device__ __forceinline__ uint32_t f2tf32(float f) {
    uint32_t r;
    asm("cvt.rna.tf32.f32 %0, %1;" : "=r"(r) : "f"(f));
    return r;
}

__device__ __forceinline__ void mma_tf32(
    float& c0, float& c1, float& c2, float& c3,
    uint32_t a0, uint32_t a1, uint32_t a2, uint32_t a3,
    uint32_t b0, uint32_t b1)
{
    asm volatile(
        "mma.sync.aligned.m16n8k8.row.col.f32.tf32.tf32.f32 "
        "{%0,%1,%2,%3}, {%4,%5,%6,%7}, {%8,%9}, {%0,%1,%2,%3};"
        : "+f"(c0), "+f"(c1), "+f"(c2), "+f"(c3)
        : "r"(a0), "r"(a1), "r"(a2), "r"(a3), "r"(b0), "r"(b1));
}

// ============ tf32 tensor-core GEMM, double-buffered ============
// 128x128x32 block tile, 8 warps, 64x32 warp tile.
// C[M,N] = A[M,K] @ B[K,N], row-major. Requires M%128==0, N%128==0, K%32==0.
#define AS_WORDS 4608            // 128*36
#define BS_WORDS 4352            // 32*136
#define STAGE_WORDS (AS_WORDS + BS_WORDS)
#define GEMM_SMEM_BYTES (2 * STAGE_WORDS * 4)   // 71680

__global__ __launch_bounds__(256, 1) void gemm_tf32(
    const float* __restrict__ A, const float* __restrict__ B,
    float* __restrict__ C, int M, int N, int K)
{
    extern __shared__ uint32_t gsm[];

    const int tid  = threadIdx.x;
    const int wid  = tid >> 5;
    const int lane = tid & 31;
    const int g    = lane >> 2;   // 0..7
    const int tg   = lane & 3;    // 0..3
    const int warp_m = (wid >> 2) * 64;
    const int warp_n = (wid & 3) * 32;

    const int m0 = blockIdx.y << 7;
    const int n0 = blockIdx.x << 7;

    const int ar  = tid >> 3;             // 0..31
    const int akq = (tid & 7) << 2;       // 0..28
    const int br  = tid >> 5;             // 0..7
    const int bc  = (tid & 31) << 2;      // 0..124

    float acc[4][4][4];
#pragma unroll
    for (int mt = 0; mt < 4; mt++)
#pragma unroll
        for (int nt = 0; nt < 4; nt++)
#pragma unroll
            for (int c = 0; c < 4; c++) acc[mt][nt][c] = 0.f;

    const int nk = K >> 5;
    float4 av[4], bv[4];

    // prologue: load tile 0, stage into buffer 0
#pragma unroll
    for (int p = 0; p < 4; p++) {
        av[p] = *(const float4*)(A + (size_t)(m0 + ar + p * 32) * K + akq);
        bv[p] = *(const float4*)(B + (size_t)(br + p * 8) * N + n0 + bc);
    }
    {
        uint32_t* As = gsm;
        uint32_t* Bs = gsm + AS_WORDS;
#pragma unroll
        for (int p = 0; p < 4; p++) {
            uint32_t* da = &As[(ar + p * 32) * 36 + akq];
            da[0] = f2tf32(av[p].x); da[1] = f2tf32(av[p].y);
            da[2] = f2tf32(av[p].z); da[3] = f2tf32(av[p].w);
            uint32_t* db = &Bs[(br + p * 8) * 136 + bc];
            db[0] = f2tf32(bv[p].x); db[1] = f2tf32(bv[p].y);
            db[2] = f2tf32(bv[p].z); db[3] = f2tf32(bv[p].w);
        }
    }

    for (int it = 0; it < nk; it++) {
        uint32_t* As = gsm + (it & 1) * STAGE_WORDS;
        uint32_t* Bs = As + AS_WORDS;
        __syncthreads();

        const bool more = (it + 1 < nk);
        if (more) {
            const int k0 = (it + 1) << 5;
#pragma unroll
            for (int p = 0; p < 4; p++) {
                av[p] = *(const float4*)(A + (size_t)(m0 + ar + p * 32) * K + k0 + akq);
                bv[p] = *(const float4*)(B + (size_t)(k0 + br + p * 8) * N + n0 + bc);
            }
        }

#pragma unroll
        for (int k8 = 0; k8 < 4; k8++) {
            const int kk = k8 * 8;
            uint32_t afr[4][4], bfr[4][2];
#pragma unroll
            for (int mt = 0; mt < 4; mt++) {
                const int m = warp_m + mt * 16;
                afr[mt][0] = As[(m + g) * 36 + kk + tg];
                afr[mt][1] = As[(m + g + 8) * 36 + kk + tg];
                afr[mt][2] = As[(m + g) * 36 + kk + tg + 4];
                afr[mt][3] = As[(m + g + 8) * 36 + kk + tg + 4];
            }
#pragma unroll
            for (int nt = 0; nt < 4; nt++) {
                const int n = warp_n + nt * 8;
                bfr[nt][0] = Bs[(kk + tg) * 136 + n + g];
                bfr[nt][1] = Bs[(kk + tg + 4) * 136 + n + g];
            }
#pragma unroll
            for (int mt = 0; mt < 4; mt++)
#pragma unroll
                for (int nt = 0; nt < 4; nt++)
                    mma_tf32(acc[mt][nt][0], acc[mt][nt][1], acc[mt][nt][2], acc[mt][nt][3],
                             afr[mt][0], afr[mt][1], afr[mt][2], afr[mt][3],
                             bfr[nt][0], bfr[nt][1]);
        }

        if (more) {
            uint32_t* Asn = gsm + ((it + 1) & 1) * STAGE_WORDS;
            uint32_t* Bsn = Asn + AS_WORDS;
#pragma unroll
            for (int p = 0; p < 4; p++) {
                uint32_t* da = &Asn[(ar + p * 32) * 36 + akq];
                da[0] = f2tf32(av[p].x); da[1] = f2tf32(av[p].y);
                da[2] = f2tf32(av[p].z); da[3] = f2tf32(av[p].w);
                uint32_t* db = &Bsn[(br + p * 8) * 136 + bc];
                db[0] = f2tf32(bv[p].x); db[1] = f2tf32(bv[p].y);
                db[2] = f2tf32(bv[p].z); db[3] = f2tf32(bv[p].w);
            }
        }
    }

#pragma unroll
    for (int mt = 0; mt < 4; mt++) {
        const int row = m0 + warp_m + mt * 16 + g;
#pragma unroll
        for (int nt = 0; nt < 4; nt++) {
            const int col = n0 + warp_n + nt * 8 + tg * 2;
            *(float2*)(C + (size_t)row * N + col)       = make_float2(acc[mt][nt][0], acc[mt][nt][1]);
            *(float2*)(C + (size_t)(row + 8) * N + col) = make_float2(acc[mt][nt][2], acc[mt][nt][3]);
        }
    }
}

// ============ 64x64x16 fp32 GEMM (kv_down: N=576, kept fp32 for accuracy) ============
__global__ __launch_bounds__(256) void gemm64(
    const float* __restrict__ A, const float* __restrict__ B,
    float* __restrict__ C, int M, int N, int K)
{
    __shared__ float As[16][64];
    __shared__ float Bs[16][64];

    const int tid = threadIdx.x;
    const int m0 = blockIdx.y << 6;
    const int n0 = blockIdx.x << 6;
    const int ty = tid >> 4;
    const int tx = tid & 15;

    const int arow = tid >> 2;
    const int acol = (tid & 3) << 2;
    const int brow = tid >> 4;
    const int bcol = (tid & 15) << 2;

    const float* Ap = A + (size_t)(m0 + arow) * K + acol;
    const float* Bp = B + (size_t)brow * N + n0 + bcol;

    float acc[4][4];
#pragma unroll
    for (int i = 0; i < 4; i++)
#pragma unroll
        for (int j = 0; j < 4; j++) acc[i][j] = 0.f;

    for (int k0 = 0; k0 < K; k0 += 16) {
        float4 a4 = *(const float4*)(Ap + k0);
        float4 b4 = *(const float4*)(Bp + (size_t)k0 * N);
        __syncthreads();
        As[acol + 0][arow] = a4.x;
        As[acol + 1][arow] = a4.y;
        As[acol + 2][arow] = a4.z;
        As[acol + 3][arow] = a4.w;
        *(float4*)&Bs[brow][bcol] = b4;
        __syncthreads();
#pragma unroll
        for (int k = 0; k < 16; k++) {
            float4 av = *(const float4*)&As[k][ty << 2];
            float4 bv = *(const float4*)&Bs[k][tx << 2];
            acc[0][0] += av.x * bv.x; acc[0][1] += av.x * bv.y;
            acc[0][2] += av.x * bv.z; acc[0][3] += av.x * bv.w;
            acc[1][0] += av.y * bv.x; acc[1][1] += av.y * bv.y;
            acc[1][2] += av.y * bv.z; acc[1][3] += av.y * bv.w;
            acc[2][0] += av.z * bv.x; acc[2][1] += av.z * bv.y;
            acc[2][2] += av.z * bv.z; acc[2][3] += av.z * bv.w;
            acc[3][0] += av.w * bv.x; acc[3][1] += av.w * bv.y;
            acc[3][2] += av.w * bv.z; acc[3][3] += av.w * bv.w;
        }
    }

    float* Cp = C + (size_t)(m0 + (ty << 2)) * N + n0 + (tx << 2);
#pragma unroll
    for (int i = 0; i < 4; i++)
        *(float4*)(Cp + (size_t)i * N) = make_float4(acc[i][0], acc[i][1], acc[i][2], acc[i][3]);
}

// ---------------- row-wise rmsnorm (in place), 256 threads ----------------
__global__ __launch_bounds__(256) void rmsnorm_rows(
    float* __restrict__ x, const float* __restrict__ w, int len)
{
    __shared__ float sb[8];
    float* row = x + (size_t)blockIdx.x * len;
    float ss = 0.f;
    for (int i = threadIdx.x; i < len; i += 256) { float v = row[i]; ss += v * v; }
    ss = warp_sum(ss);
    if ((threadIdx.x & 31) == 0) sb[threadIdx.x >> 5] = ss;
    __syncthreads();
    float tot = 0.f;
#pragma unroll
    for (int i = 0; i < 8; i++) tot += sb[i];
    float sc = rsqrtf(tot / (float)len + EPSV);
    for (int i = threadIdx.x; i < len; i += 256) row[i] = row[i] * sc * w[i];
}

// ---------------- build q ----------------
__global__ __launch_bounds__(128) void q_build(
    const float* __restrict__ qn, const float* __restrict__ qr,
    const float* __restrict__ qhw,
    const float* __restrict__ fc, const float* __restrict__ fs,
    float* __restrict__ q)
{
    __shared__ float sb[4];
    const int token = blockIdx.y, h = blockIdx.x;
    const int t = token & (TSEQ - 1);
    const float* xn = qn + (size_t)token * NH * NND + h * NND;
    float v = xn[threadIdx.x];
    float ss = warp_sum(v * v);
    if ((threadIdx.x & 31) == 0) sb[threadIdx.x >> 5] = ss;
    __syncthreads();
    float tot = sb[0] + sb[1] + sb[2] + sb[3];
    float sc = rsqrtf(tot / (float)NND + EPSV);
    float* qo = q + ((size_t)token * NH + h) * DQK;
    qo[threadIdx.x] = v * sc * qhw[threadIdx.x];
    if (threadIdx.x < NRD / 2) {
        int i = threadIdx.x;
        const float* xr = qr + (size_t)token * NH * NRD + h * NRD;
        float a = xr[2 * i], b = xr[2 * i + 1];
        float c = fc[t * (NRD / 2) + i], s = fs[t * (NRD / 2) + i];
        qo[NND + 2 * i]     = a * c - b * s;
        qo[NND + 2 * i + 1] = a * s + b * c;
    }
}

// ---------------- kv post ----------------
__global__ __launch_bounds__(128) void kv_post(
    const float* __restrict__ kvraw, const float* __restrict__ kvw,
    const float* __restrict__ fc, const float* __restrict__ fs,
    float* __restrict__ ckv, float* __restrict__ kr)
{
    __shared__ float sb[4];
    const int token = blockIdx.x;
    const int t = token & (TSEQ - 1);
    const float* row = kvraw + (size_t)token * (NKVLR + NRD);
    float ss = 0.f;
    for (int i = threadIdx.x; i < NKVLR; i += 128) { float v = row[i]; ss += v * v; }
    ss = warp_sum(ss);
    if ((threadIdx.x & 31) == 0) sb[threadIdx.x >> 5] = ss;
    __syncthreads();
    float tot = sb[0] + sb[1] + sb[2] + sb[3];
    float sc = rsqrtf(tot / (float)NKVLR + EPSV);
    for (int i = threadIdx.x; i < NKVLR; i += 128)
        ckv[(size_t)token * NKVLR + i] = row[i] * sc * kvw[i];
    if (threadIdx.x < NRD / 2) {
        int i = threadIdx.x;
        float a = row[NKVLR + 2 * i], b = row[NKVLR + 2 * i + 1];
        float c = fc[t * (NRD / 2) + i], s = fs[t * (NRD / 2) + i];
        kr[(size_t)token * NRD + 2 * i]     = a * c - b * s;
        kr[(size_t)token * NRD + 2 * i + 1] = a * s + b * c;
    }
}

// ---------------- build k ----------------
__global__ __launch_bounds__(128) void k_build(
    const float* __restrict__ kv, const float* __restrict__ khw,
    const float* __restrict__ kr, float* __restrict__ k)
{
    __shared__ float sb[4];
    const int token = blockIdx.y, h = blockIdx.x;
    const float* kn = kv + ((size_t)token * NH + h) * (NND + NVD);
    float v = kn[threadIdx.x];
    float ss = warp_sum(v * v);
    if ((threadIdx.x & 31) == 0) sb[threadIdx.x >> 5] = ss;
    __syncthreads();
    float tot = sb[0] + sb[1] + sb[2] + sb[3];
    float sc = rsqrtf(tot / (float)NND + EPSV);
    float* ko = k + ((size_t)token * NH + h) * DQK;
    ko[threadIdx.x] = v * sc * khw[threadIdx.x];
    if (threadIdx.x < NRD) ko[NND + threadIdx.x] = kr[(size_t)token * NRD + threadIdx.x];
}

// ============ causal flash attention v3: full Q/K tiles in smem ============
// grid: (TSEQ/64, B*H), block 256 = 16x16. Thread: 4 score rows x 4 cols, 4x8 out.
// Dynamic smem (floats): Qs[192][68] @0, Ks[192][68] @13056, Ps[64][68] @26112,
//                        Vs[64][132] @30464. Total 38912 floats = 155648 B.
#define ATTN_SMEM_BYTES (38912 * 4)

__global__ __launch_bounds__(256) void attn_kernel(
    const float* __restrict__ q, const float* __restrict__ k,
    const float* __restrict__ kv, float* __restrict__ ao)
{
    extern __shared__ float sm[];
    float* Qs = sm;            // [d][m] stride 68, d=0..191
    float* Ks = sm + 13056;    // [d][n] stride 68
    float* Ps = sm + 26112;    // [i][j] stride 68
    float* Vs = sm + 30464;    // [j][c] stride 132

    const int tid = threadIdx.x;
    const int ty = tid >> 4, tx = tid & 15;
    const int qt = (int)gridDim.x - 1 - (int)blockIdx.x;
    const int bh = blockIdx.y;
    const int b = bh >> 4, h = bh & 15;
    const int qt0 = qt << 6;
    const int bT = b * TSEQ;
    const float SCALE = 0.07216878364870322f;

    const float* qh = q  + ((size_t)(bT + qt0) * NH + h) * DQK;
    const float* vh = kv + ((size_t)bT * NH + h) * (NND + NVD) + NND;

    const int ldj = tid >> 3;     // 0..31
    const int ldd = tid & 7;      // 0..7

    // ---- load full Q tile once (transposed [d][m]) ----
#pragma unroll
    for (int dc = 0; dc < 6; dc++) {
        const int doff = dc * 32 + ldd * 4;
#pragma unroll
        for (int p = 0; p < 2; p++) {
            int jr = (p << 5) + ldj;
            float4 a = *(const float4*)(qh + (size_t)jr * (NH * DQK) + doff);
            float* dq = &Qs[(size_t)doff * 68 + jr];
            dq[0] = a.x; dq[68] = a.y; dq[136] = a.z; dq[204] = a.w;
        }
    }

    float rm[4], rl[4], acc[4][8];
#pragma unroll
    for (int i = 0; i < 4; i++) { rm[i] = -1e30f; rl[i] = 0.f; }
#pragma unroll
    for (int i = 0; i < 4; i++)
#pragma unroll
        for (int c = 0; c < 8; c++) acc[i][c] = 0.f;

    for (int kt = 0; kt <= qt; kt++) {
        const int kt0 = kt << 6;
        const float* kh = k + ((size_t)(bT + kt0) * NH + h) * DQK;

        // ---- load full K tile (transposed) + V tile ----
#pragma unroll
        for (int dc = 0; dc < 6; dc++) {
            const int doff = dc * 32 + ldd * 4;
#pragma unroll
            for (int p = 0; p < 2; p++) {
                int jr = (p << 5) + ldj;
                float4 a = *(const float4*)(kh + (size_t)jr * (NH * DQK) + doff);
                float* dk = &Ks[(size_t)doff * 68 + jr];
                dk[0] = a.x; dk[68] = a.y; dk[136] = a.z; dk[204] = a.w;
            }
        }
#pragma unroll
        for (int p = 0; p < 8; p++) {
            int e = p * 256 + tid;
            int j = e >> 5, cg = (e & 31) << 2;
            float4 v4 = *(const float4*)(vh + (size_t)(kt0 + j) * (NH * (NND + NVD)) + cg);
            *(float4*)&Vs[j * 132 + cg] = v4;
        }
        __syncthreads();   // Q (iter 0), K, V visible

        // ---- scores: single 192-deep loop ----
        float sreg[4][4];
#pragma unroll
        for (int i = 0; i < 4; i++)
#pragma unroll
            for (int j = 0; j < 4; j++) sreg[i][j] = 0.f;

#pragma unroll 8
        for (int dd = 0; dd < DQK; dd++) {
            float4 qv  = *(const float4*)&Qs[dd * 68 + (ty << 2)];
            float4 kv4 = *(const float4*)&Ks[dd * 68 + (tx << 2)];
            float qa[4] = {qv.x, qv.y, qv.z, qv.w};
            float kb[4] = {kv4.x, kv4.y, kv4.z, kv4.w};
#pragma unroll
            for (int i = 0; i < 4; i++)
#pragma unroll
                for (int j = 0; j < 4; j++) sreg[i][j] += qa[i] * kb[j];
        }

#pragma unroll
        for (int i = 0; i < 4; i++)
#pragma unroll
            for (int j = 0; j < 4; j++) sreg[i][j] *= SCALE;
        if (kt == qt) {
#pragma unroll
            for (int i = 0; i < 4; i++) {
                int ir = ty * 4 + i;
#pragma unroll
                for (int j = 0; j < 4; j++)
                    if (tx * 4 + j > ir) sreg[i][j] = -1e30f;
            }
        }

        // ---- online softmax ----
#pragma unroll
        for (int i = 0; i < 4; i++) {
            float mt = fmaxf(fmaxf(sreg[i][0], sreg[i][1]), fmaxf(sreg[i][2], sreg[i][3]));
            mt = fmaxf(mt, __shfl_xor_sync(0xffffffffu, mt, 1));
            mt = fmaxf(mt, __shfl_xor_sync(0xffffffffu, mt, 2));
            mt = fmaxf(mt, __shfl_xor_sync(0xffffffffu, mt, 4));
            mt = fmaxf(mt, __shfl_xor_sync(0xffffffffu, mt, 8));
            float mn = fmaxf(rm[i], mt);
            float corr = __expf(rm[i] - mn);
            float ps = 0.f;
#pragma unroll
            for (int j = 0; j < 4; j++) {
                float e = __expf(sreg[i][j] - mn);
                sreg[i][j] = e;
                ps += e;
            }
            ps += __shfl_xor_sync(0xffffffffu, ps, 1);
            ps += __shfl_xor_sync(0xffffffffu, ps, 2);
            ps += __shfl_xor_sync(0xffffffffu, ps, 4);
            ps += __shfl_xor_sync(0xffffffffu, ps, 8);
            rl[i] = rl[i] * corr + ps;
            rm[i] = mn;
#pragma unroll
            for (int c = 0; c < 8; c++) acc[i][c] *= corr;
            *(float4*)&Ps[(ty * 4 + i) * 68 + (tx << 2)] =
                make_float4(sreg[i][0], sreg[i][1], sreg[i][2], sreg[i][3]);
        }
        __syncthreads();   // Ps visible

        // ---- PV ----
#pragma unroll 4
        for (int j = 0; j < 64; j++) {
            float p0 = Ps[(ty * 4 + 0) * 68 + j];
            float p1 = Ps[(ty * 4 + 1) * 68 + j];
            float p2 = Ps[(ty * 4 + 2) * 68 + j];
            float p3 = Ps[(ty * 4 + 3) * 68 + j];
            float4 v0 = *(const float4*)&Vs[j * 132 + (tx << 2)];
            float4 v1 = *(const float4*)&Vs[j * 132 + 64 + (tx << 2)];
            float vb[8] = {v0.x, v0.y, v0.z, v0.w, v1.x, v1.y, v1.z, v1.w};
#pragma unroll
            for (int c = 0; c < 8; c++) {
                acc[0][c] += p0 * vb[c];
                acc[1][c] += p1 * vb[c];
                acc[2][c] += p2 * vb[c];
                acc[3][c] += p3 * vb[c];
            }
        }
        __syncthreads();   // all reads of Ks/Vs/Ps done before next overwrite
    }

#pragma unroll
    for (int i = 0; i < 4; i++) {
        float inv = 1.f / rl[i];
        int tok = qt0 + ty * 4 + i;
        float* op = ao + ((size_t)(bT + tok) * NH + h) * NVD;
        *(float4*)(op + (tx << 2))      = make_float4(acc[i][0] * inv, acc[i][1] * inv,
                                                      acc[i][2] * inv, acc[i][3] * inv);
        *(float4*)(op + 64 + (tx << 2)) = make_float4(acc[i][4] * inv, acc[i][5] * inv,
                                                      acc[i][6] * inv, acc[i][7] * inv);
    }
}

// ---------------- launch ----------------
extern "C" void kernel_launch(void* const* d_in, const int* in_sizes, int n_in,
                              void* d_out, int out_size)
{
    const float* x    = (const float*)d_in[0];
    const float* fc   = (const float*)d_in[1];
    const float* fs   = (const float*)d_in[2];
    const float* qdw  = (const float*)d_in[3];
    const float* qnw  = (const float*)d_in[4];
    const float* qunw = (const float*)d_in[5];
    const float* qurw = (const float*)d_in[6];
    const float* kdw  = (const float*)d_in[7];
    const float* kvnw = (const float*)d_in[8];
    const float* kuw  = (const float*)d_in[9];
    const float* qhw  = (const float*)d_in[10];
    const float* khw  = (const float*)d_in[11];
    const float* wow  = (const float*)d_in[12];
    float* out = (float*)d_out;

    float *p_cq, *p_qn, *p_qr, *p_q, *p_kvraw, *p_ckv, *p_kr, *p_kv, *p_k, *p_ao;
    cudaGetSymbolAddress((void**)&p_cq,    g_cq);
    cudaGetSymbolAddress((void**)&p_qn,    g_qn);
    cudaGetSymbolAddress((void**)&p_qr,    g_qr);
    cudaGetSymbolAddress((void**)&p_q,     g_q);
    cudaGetSymbolAddress((void**)&p_kvraw, g_kvraw);
    cudaGetSymbolAddress((void**)&p_ckv,   g_ckv);
    cudaGetSymbolAddress((void**)&p_kr,    g_kr);
    cudaGetSymbolAddress((void**)&p_kv,    g_kv);
    cudaGetSymbolAddress((void**)&p_k,     g_k);
    cudaGetSymbolAddress((void**)&p_ao,    g_ao);

    cudaFuncSetAttribute(gemm_tf32, cudaFuncAttributeMaxDynamicSharedMemorySize,
                         GEMM_SMEM_BYTES);
    cudaFuncSetAttribute(attn_kernel, cudaFuncAttributeMaxDynamicSharedMemorySize,
                         ATTN_SMEM_BYTES);

    // c_q = x @ q_down_w ; rmsnorm
    gemm_tf32<<<dim3(NQLR / 128, NTOK / 128), 256, GEMM_SMEM_BYTES>>>(x, qdw, p_cq, NTOK, NQLR, NDIM);
    rmsnorm_rows<<<NTOK, 256>>>(p_cq, qnw, NQLR);

    // q projections
    gemm_tf32<<<dim3((NH * NND) / 128, NTOK / 128), 256, GEMM_SMEM_BYTES>>>(p_cq, qunw, p_qn, NTOK, NH * NND, NQLR);
    gemm_tf32<<<dim3((NH * NRD) / 128, NTOK / 128), 256, GEMM_SMEM_BYTES>>>(p_cq, qurw, p_qr, NTOK, NH * NRD, NQLR);

    // kv down (N=576, fp32 for accuracy margin)
    gemm64<<<dim3((NKVLR + NRD) / 64, NTOK / 64), 256>>>(x, kdw, p_kvraw, NTOK, NKVLR + NRD, NDIM);

    // epilogues
    q_build<<<dim3(NH, NTOK), 128>>>(p_qn, p_qr, qhw, fc, fs, p_q);
    kv_post<<<NTOK, 128>>>(p_kvraw, kvnw, fc, fs, p_ckv, p_kr);

    // kv up + k build
    gemm_tf32<<<dim3((NH * (NND + NVD)) / 128, NTOK / 128), 256, GEMM_SMEM_BYTES>>>(p_ckv, kuw, p_kv, NTOK, NH * (NND + NVD), NKVLR);
    k_build<<<dim3(NH, NTOK), 128>>>(p_kv, khw, p_kr, p_k);

    // attention
    attn_kernel<<<dim3(TSEQ / 64, NB * NH), 256, ATTN_SMEM_BYTES>>>(p_q, p_k, p_kv, p_ao);

    // output projection
    gemm_tf32<<<dim3(NDIM / 128, NTOK / 128), 256, GEMM_SMEM_BYTES>>>(p_ao, wow, out, NTOK, NDIM, NH * NVD);
}

// round 12
// speedup vs baseline: 4.2583x; 1.1110x over previous
#include <cuda_runtime.h>
#include <math.h>
#include <stdint.h>

// ---------------- problem constants ----------------
#define NB      2
#define TSEQ    2048
#define NDIM    2048
#define NH      16
#define NQLR    1536
#define NKVLR   512
#define NRD     64
#define NND     128
#define NVD     128
#define NTOK    (NB * TSEQ)        // 4096
#define DQK     (NND + NRD)        // 192
#define KVP     640                 // padded kv_down output width (576 -> 640)
#define EPSV    1e-6f

// ---------------- scratch (no allocations allowed) ----------------
__device__ float g_cq     [(size_t)NTOK * NQLR];
__device__ float g_qn     [(size_t)NTOK * NH * NND];
__device__ float g_qr     [(size_t)NTOK * NH * NRD];
__device__ float g_q      [(size_t)NTOK * NH * DQK];
__device__ float g_kvraw  [(size_t)NTOK * KVP];
__device__ float g_ckv    [(size_t)NTOK * NKVLR];
__device__ float g_kr     [(size_t)NTOK * NRD];
__device__ float g_kv     [(size_t)NTOK * NH * (NND + NVD)];
__device__ float g_k      [(size_t)NTOK * NH * DQK];
__device__ float g_ao     [(size_t)NTOK * NH * NVD];
__device__ float g_kdwpad [(size_t)NDIM * KVP];

// ---------------- helpers ----------------
__device__ __forceinline__ float warp_sum(float v) {
#pragma unroll
    for (int o = 16; o; o >>= 1) v += __shfl_xor_sync(0xffffffffu, v, o);
    return v;
}

__device__ __forceinline__ uint32_t f2tf32(float f) {
    uint32_t r;
    asm("cvt.rna.tf32.f32 %0, %1;" : "=r"(r) : "f"(f));
    return r;
}

__device__ __forceinline__ void mma_tf32(
    float& c0, float& c1, float& c2, float& c3,
    uint32_t a0, uint32_t a1, uint32_t a2, uint32_t a3,
    uint32_t b0, uint32_t b1)
{
    asm volatile(
        "mma.sync.aligned.m16n8k8.row.col.f32.tf32.tf32.f32 "
        "{%0,%1,%2,%3}, {%4,%5,%6,%7}, {%8,%9}, {%0,%1,%2,%3};"
        : "+f"(c0), "+f"(c1), "+f"(c2), "+f"(c3)
        : "r"(a0), "r"(a1), "r"(a2), "r"(a3), "r"(b0), "r"(b1));
}

__device__ __forceinline__ void cp16(uint32_t dst_smem, const void* src) {
    asm volatile("cp.async.cg.shared.global [%0], [%1], 16;\n"
                 :: "r"(dst_smem), "l"(src) : "memory");
}
#define CP_COMMIT() asm volatile("cp.async.commit_group;\n" ::: "memory")
#define CP_WAIT(N)  asm volatile("cp.async.wait_group %0;\n" :: "n"(N) : "memory")

// ============ tf32 tensor-core GEMM, double-buffered ============
// 128x128x32 block tile, 8 warps, 64x32 warp tile.
// C[M,N] = A[M,K] @ B[K,N], row-major. M%128==0, N%128==0, K%32==0.
#define AS_WORDS 4608            // 128*36
#define BS_WORDS 4352            // 32*136
#define STAGE_WORDS (AS_WORDS + BS_WORDS)
#define GEMM_SMEM_BYTES (2 * STAGE_WORDS * 4)   // 71680

__global__ __launch_bounds__(256, 1) void gemm_tf32(
    const float* __restrict__ A, const float* __restrict__ B,
    float* __restrict__ C, int M, int N, int K)
{
    extern __shared__ uint32_t gsm[];

    const int tid  = threadIdx.x;
    const int wid  = tid >> 5;
    const int lane = tid & 31;
    const int g    = lane >> 2;
    const int tg   = lane & 3;
    const int warp_m = (wid >> 2) * 64;
    const int warp_n = (wid & 3) * 32;

    const int m0 = blockIdx.y << 7;
    const int n0 = blockIdx.x << 7;

    const int ar  = tid >> 3;
    const int akq = (tid & 7) << 2;
    const int br  = tid >> 5;
    const int bc  = (tid & 31) << 2;

    float acc[4][4][4];
#pragma unroll
    for (int mt = 0; mt < 4; mt++)
#pragma unroll
        for (int nt = 0; nt < 4; nt++)
#pragma unroll
            for (int c = 0; c < 4; c++) acc[mt][nt][c] = 0.f;

    const int nk = K >> 5;
    float4 av[4], bv[4];

#pragma unroll
    for (int p = 0; p < 4; p++) {
        av[p] = *(const float4*)(A + (size_t)(m0 + ar + p * 32) * K + akq);
        bv[p] = *(const float4*)(B + (size_t)(br + p * 8) * N + n0 + bc);
    }
    {
        uint32_t* As = gsm;
        uint32_t* Bs = gsm + AS_WORDS;
#pragma unroll
        for (int p = 0; p < 4; p++) {
            uint32_t* da = &As[(ar + p * 32) * 36 + akq];
            da[0] = f2tf32(av[p].x); da[1] = f2tf32(av[p].y);
            da[2] = f2tf32(av[p].z); da[3] = f2tf32(av[p].w);
            uint32_t* db = &Bs[(br + p * 8) * 136 + bc];
            db[0] = f2tf32(bv[p].x); db[1] = f2tf32(bv[p].y);
            db[2] = f2tf32(bv[p].z); db[3] = f2tf32(bv[p].w);
        }
    }

    for (int it = 0; it < nk; it++) {
        uint32_t* As = gsm + (it & 1) * STAGE_WORDS;
        uint32_t* Bs = As + AS_WORDS;
        __syncthreads();

        const bool more = (it + 1 < nk);
        if (more) {
            const int k0 = (it + 1) << 5;
#pragma unroll
            for (int p = 0; p < 4; p++) {
                av[p] = *(const float4*)(A + (size_t)(m0 + ar + p * 32) * K + k0 + akq);
                bv[p] = *(const float4*)(B + (size_t)(k0 + br + p * 8) * N + n0 + bc);
            }
        }

#pragma unroll
        for (int k8 = 0; k8 < 4; k8++) {
            const int kk = k8 * 8;
            uint32_t afr[4][4], bfr[4][2];
#pragma unroll
            for (int mt = 0; mt < 4; mt++) {
                const int m = warp_m + mt * 16;
                afr[mt][0] = As[(m + g) * 36 + kk + tg];
                afr[mt][1] = As[(m + g + 8) * 36 + kk + tg];
                afr[mt][2] = As[(m + g) * 36 + kk + tg + 4];
                afr[mt][3] = As[(m + g + 8) * 36 + kk + tg + 4];
            }
#pragma unroll
            for (int nt = 0; nt < 4; nt++) {
                const int n = warp_n + nt * 8;
                bfr[nt][0] = Bs[(kk + tg) * 136 + n + g];
                bfr[nt][1] = Bs[(kk + tg + 4) * 136 + n + g];
            }
#pragma unroll
            for (int mt = 0; mt < 4; mt++)
#pragma unroll
                for (int nt = 0; nt < 4; nt++)
                    mma_tf32(acc[mt][nt][0], acc[mt][nt][1], acc[mt][nt][2], acc[mt][nt][3],
                             afr[mt][0], afr[mt][1], afr[mt][2], afr[mt][3],
                             bfr[nt][0], bfr[nt][1]);
        }

        if (more) {
            uint32_t* Asn = gsm + ((it + 1) & 1) * STAGE_WORDS;
            uint32_t* Bsn = Asn + AS_WORDS;
#pragma unroll
            for (int p = 0; p < 4; p++) {
                uint32_t* da = &Asn[(ar + p * 32) * 36 + akq];
                da[0] = f2tf32(av[p].x); da[1] = f2tf32(av[p].y);
                da[2] = f2tf32(av[p].z); da[3] = f2tf32(av[p].w);
                uint32_t* db = &Bsn[(br + p * 8) * 136 + bc];
                db[0] = f2tf32(bv[p].x); db[1] = f2tf32(bv[p].y);
                db[2] = f2tf32(bv[p].z); db[3] = f2tf32(bv[p].w);
            }
        }
    }

#pragma unroll
    for (int mt = 0; mt < 4; mt++) {
        const int row = m0 + warp_m + mt * 16 + g;
#pragma unroll
        for (int nt = 0; nt < 4; nt++) {
            const int col = n0 + warp_n + nt * 8 + tg * 2;
            *(float2*)(C + (size_t)row * N + col)       = make_float2(acc[mt][nt][0], acc[mt][nt][1]);
            *(float2*)(C + (size_t)(row + 8) * N + col) = make_float2(acc[mt][nt][2], acc[mt][nt][3]);
        }
    }
}

// ---------------- pad kv_down_w (2048x576) into (2048x640), zero-filled ----------------
__global__ __launch_bounds__(256) void pad_kdw(
    const float* __restrict__ w, float* __restrict__ o)
{
    int idx = blockIdx.x * 256 + threadIdx.x;     // 0 .. 2048*640-1
    int r = idx / KVP, c = idx - r * KVP;
    o[idx] = (c < NKVLR + NRD) ? w[r * (NKVLR + NRD) + c] : 0.f;
}

// ---------------- row-wise rmsnorm (in place), 256 threads ----------------
__global__ __launch_bounds__(256) void rmsnorm_rows(
    float* __restrict__ x, const float* __restrict__ w, int len)
{
    __shared__ float sb[8];
    float* row = x + (size_t)blockIdx.x * len;
    float ss = 0.f;
    for (int i = threadIdx.x; i < len; i += 256) { float v = row[i]; ss += v * v; }
    ss = warp_sum(ss);
    if ((threadIdx.x & 31) == 0) sb[threadIdx.x >> 5] = ss;
    __syncthreads();
    float tot = 0.f;
#pragma unroll
    for (int i = 0; i < 8; i++) tot += sb[i];
    float sc = rsqrtf(tot / (float)len + EPSV);
    for (int i = threadIdx.x; i < len; i += 256) row[i] = row[i] * sc * w[i];
}

// ---------------- build q ----------------
__global__ __launch_bounds__(128) void q_build(
    const float* __restrict__ qn, const float* __restrict__ qr,
    const float* __restrict__ qhw,
    const float* __restrict__ fc, const float* __restrict__ fs,
    float* __restrict__ q)
{
    __shared__ float sb[4];
    const int token = blockIdx.y, h = blockIdx.x;
    const int t = token & (TSEQ - 1);
    const float* xn = qn + (size_t)token * NH * NND + h * NND;
    float v = xn[threadIdx.x];
    float ss = warp_sum(v * v);
    if ((threadIdx.x & 31) == 0) sb[threadIdx.x >> 5] = ss;
    __syncthreads();
    float tot = sb[0] + sb[1] + sb[2] + sb[3];
    float sc = rsqrtf(tot / (float)NND + EPSV);
    float* qo = q + ((size_t)token * NH + h) * DQK;
    qo[threadIdx.x] = v * sc * qhw[threadIdx.x];
    if (threadIdx.x < NRD / 2) {
        int i = threadIdx.x;
        const float* xr = qr + (size_t)token * NH * NRD + h * NRD;
        float a = xr[2 * i], b = xr[2 * i + 1];
        float c = fc[t * (NRD / 2) + i], s = fs[t * (NRD / 2) + i];
        qo[NND + 2 * i]     = a * c - b * s;
        qo[NND + 2 * i + 1] = a * s + b * c;
    }
}

// ---------------- kv post (reads padded kvraw, stride KVP) ----------------
__global__ __launch_bounds__(128) void kv_post(
    const float* __restrict__ kvraw, const float* __restrict__ kvw,
    const float* __restrict__ fc, const float* __restrict__ fs,
    float* __restrict__ ckv, float* __restrict__ kr)
{
    __shared__ float sb[4];
    const int token = blockIdx.x;
    const int t = token & (TSEQ - 1);
    const float* row = kvraw + (size_t)token * KVP;
    float ss = 0.f;
    for (int i = threadIdx.x; i < NKVLR; i += 128) { float v = row[i]; ss += v * v; }
    ss = warp_sum(ss);
    if ((threadIdx.x & 31) == 0) sb[threadIdx.x >> 5] = ss;
    __syncthreads();
    float tot = sb[0] + sb[1] + sb[2] + sb[3];
    float sc = rsqrtf(tot / (float)NKVLR + EPSV);
    for (int i = threadIdx.x; i < NKVLR; i += 128)
        ckv[(size_t)token * NKVLR + i] = row[i] * sc * kvw[i];
    if (threadIdx.x < NRD / 2) {
        int i = threadIdx.x;
        float a = row[NKVLR + 2 * i], b = row[NKVLR + 2 * i + 1];
        float c = fc[t * (NRD / 2) + i], s = fs[t * (NRD / 2) + i];
        kr[(size_t)token * NRD + 2 * i]     = a * c - b * s;
        kr[(size_t)token * NRD + 2 * i + 1] = a * s + b * c;
    }
}

// ---------------- build k ----------------
__global__ __launch_bounds__(128) void k_build(
    const float* __restrict__ kv, const float* __restrict__ khw,
    const float* __restrict__ kr, float* __restrict__ k)
{
    __shared__ float sb[4];
    const int token = blockIdx.y, h = blockIdx.x;
    const float* kn = kv + ((size_t)token * NH + h) * (NND + NVD);
    float v = kn[threadIdx.x];
    float ss = warp_sum(v * v);
    if ((threadIdx.x & 31) == 0) sb[threadIdx.x >> 5] = ss;
    __syncthreads();
    float tot = sb[0] + sb[1] + sb[2] + sb[3];
    float sc = rsqrtf(tot / (float)NND + EPSV);
    float* ko = k + ((size_t)token * NH + h) * DQK;
    ko[threadIdx.x] = v * sc * khw[threadIdx.x];
    if (threadIdx.x < NRD) ko[NND + threadIdx.x] = kr[(size_t)token * NRD + threadIdx.x];
}

// ============ causal flash attention v4.1: row-major smem + cp.async pipeline ============
// grid: (TSEQ/64, B*H), block 256 = 16(ty) x 16(tx).
// Thread: score microtile 4 rows (ty*4+i) x 4 keys (tx+16j); out 4 rows x 8 cols.
// Q/K loader: 4 threads per row, each loads 12 quads (48 quads = 192 floats per row).
// Smem (floats): Qs[64][196] @0, Ks[2][64][196] @12544, Vs[64][132] @37632,
//                Ps[64][68] @46080. Total 50432 floats = 201728 B.
#define QS_OFF 0
#define KS_OFF 12544
#define KS_SZ  12544
#define VS_OFF 37632
#define PS_OFF 46080
#define ATTN_SMEM_BYTES (50432 * 4)

__global__ __launch_bounds__(256) void attn_kernel(
    const float* __restrict__ q, const float* __restrict__ k,
    const float* __restrict__ kv, float* __restrict__ ao)
{
    extern __shared__ float sm[];
    float* Qs = sm + QS_OFF;               // [m][196]
    float* Ps = sm + PS_OFF;               // [i][68]
    float* Vs = sm + VS_OFF;               // [j][132]
    const uint32_t smb = (uint32_t)__cvta_generic_to_shared(sm);

    const int tid = threadIdx.x;
    const int ty = tid >> 4, tx = tid & 15;
    const int qt = (int)gridDim.x - 1 - (int)blockIdx.x;
    const int bh = blockIdx.y;
    const int b = bh >> 4, h = bh & 15;
    const int qt0 = qt << 6;
    const int bT = b * TSEQ;
    const float SCALE = 0.07216878364870322f;

    const float* qh = q  + ((size_t)(bT + qt0) * NH + h) * DQK;
    const float* vh = kv + ((size_t)bT * NH + h) * (NND + NVD) + NND;

    // loader indices: 4 threads per row, 12 quads each (48 quads = 192 floats/row)
    const int lrow = tid >> 2;            // 0..63
    const int lq0  = (tid & 3) * 12;      // quad base: 0,12,24,36

    // ---- prologue: async Q + K0 (group), V0 (group) ----
#pragma unroll
    for (int p = 0; p < 12; p++) {
        int quad = lq0 + p;
        cp16(smb + (QS_OFF + lrow * 196 + quad * 4) * 4,
             qh + (size_t)lrow * (NH * DQK) + quad * 4);
    }
    {
        const float* kh0 = k + ((size_t)bT * NH + h) * DQK;
#pragma unroll
        for (int p = 0; p < 12; p++) {
            int quad = lq0 + p;
            cp16(smb + (KS_OFF + lrow * 196 + quad * 4) * 4,
                 kh0 + (size_t)lrow * (NH * DQK) + quad * 4);
        }
    }
    CP_COMMIT();   // group A: Q + K0
#pragma unroll
    for (int p = 0; p < 8; p++) {
        int c = p * 256 + tid;
        int j = c >> 5, off = (c & 31) * 4;
        cp16(smb + (VS_OFF + j * 132 + off) * 4,
             vh + (size_t)j * (NH * (NND + NVD)) + off);
    }
    CP_COMMIT();   // group B: V0

    float rm[4], rl[4], acc[4][8];
#pragma unroll
    for (int i = 0; i < 4; i++) { rm[i] = -1e30f; rl[i] = 0.f; }
#pragma unroll
    for (int i = 0; i < 4; i++)
#pragma unroll
        for (int c = 0; c < 8; c++) acc[i][c] = 0.f;

    for (int kt = 0; kt <= qt; kt++) {
        // entering: pending = {K(kt)(+Q at kt=0), V(kt)}  ->  retire K group
        CP_WAIT(1);
        __syncthreads();

        // prefetch K(kt+1) into the other buffer
        if (kt < qt) {
            const float* khn = k + ((size_t)(bT + (kt + 1) * 64) * NH + h) * DQK;
            const uint32_t kdst = smb + (KS_OFF + ((kt + 1) & 1) * KS_SZ) * 4;
#pragma unroll
            for (int p = 0; p < 12; p++) {
                int quad = lq0 + p;
                cp16(kdst + (lrow * 196 + quad * 4) * 4,
                     khn + (size_t)lrow * (NH * DQK) + quad * 4);
            }
            CP_COMMIT();
        }

        const float* Ks = sm + KS_OFF + (kt & 1) * KS_SZ;

        // ---- scores: 4x4 microtile, keys n = tx + 16j ----
        float sreg[4][4];
#pragma unroll
        for (int i = 0; i < 4; i++)
#pragma unroll
            for (int j = 0; j < 4; j++) sreg[i][j] = 0.f;

#pragma unroll 4
        for (int dd = 0; dd < DQK; dd += 4) {
            float4 qa[4], kb[4];
#pragma unroll
            for (int i = 0; i < 4; i++)
                qa[i] = *(const float4*)&Qs[(ty * 4 + i) * 196 + dd];
#pragma unroll
            for (int j = 0; j < 4; j++)
                kb[j] = *(const float4*)&Ks[(tx + 16 * j) * 196 + dd];
#pragma unroll
            for (int i = 0; i < 4; i++)
#pragma unroll
                for (int j = 0; j < 4; j++) {
                    sreg[i][j] += qa[i].x * kb[j].x + qa[i].y * kb[j].y
                                + qa[i].z * kb[j].z + qa[i].w * kb[j].w;
                }
        }

#pragma unroll
        for (int i = 0; i < 4; i++)
#pragma unroll
            for (int j = 0; j < 4; j++) sreg[i][j] *= SCALE;
        if (kt == qt) {
#pragma unroll
            for (int i = 0; i < 4; i++) {
                int ir = ty * 4 + i;
#pragma unroll
                for (int j = 0; j < 4; j++)
                    if (tx + 16 * j > ir) sreg[i][j] = -1e30f;
            }
        }

        // ---- online softmax (16-lane row groups) ----
#pragma unroll
        for (int i = 0; i < 4; i++) {
            float mt = fmaxf(fmaxf(sreg[i][0], sreg[i][1]), fmaxf(sreg[i][2], sreg[i][3]));
            mt = fmaxf(mt, __shfl_xor_sync(0xffffffffu, mt, 1));
            mt = fmaxf(mt, __shfl_xor_sync(0xffffffffu, mt, 2));
            mt = fmaxf(mt, __shfl_xor_sync(0xffffffffu, mt, 4));
            mt = fmaxf(mt, __shfl_xor_sync(0xffffffffu, mt, 8));
            float mn = fmaxf(rm[i], mt);
            float corr = __expf(rm[i] - mn);
            float ps = 0.f;
#pragma unroll
            for (int j = 0; j < 4; j++) {
                float e = __expf(sreg[i][j] - mn);
                sreg[i][j] = e;
                ps += e;
            }
            ps += __shfl_xor_sync(0xffffffffu, ps, 1);
            ps += __shfl_xor_sync(0xffffffffu, ps, 2);
            ps += __shfl_xor_sync(0xffffffffu, ps, 4);
            ps += __shfl_xor_sync(0xffffffffu, ps, 8);
            rl[i] = rl[i] * corr + ps;
            rm[i] = mn;
#pragma unroll
            for (int c = 0; c < 8; c++) acc[i][c] *= corr;
#pragma unroll
            for (int j = 0; j < 4; j++)
                Ps[(ty * 4 + i) * 68 + tx + 16 * j] = sreg[i][j];
        }

        // retire V(kt) before PV (K(kt+1) may remain in flight)
        if (kt < qt) { CP_WAIT(1); } else { CP_WAIT(0); }
        __syncthreads();

        // ---- PV ----
#pragma unroll 4
        for (int j = 0; j < 64; j++) {
            float p0 = Ps[(ty * 4 + 0) * 68 + j];
            float p1 = Ps[(ty * 4 + 1) * 68 + j];
            float p2 = Ps[(ty * 4 + 2) * 68 + j];
            float p3 = Ps[(ty * 4 + 3) * 68 + j];
            float4 v0 = *(const float4*)&Vs[j * 132 + (tx << 2)];
            float4 v1 = *(const float4*)&Vs[j * 132 + 64 + (tx << 2)];
            float vb[8] = {v0.x, v0.y, v0.z, v0.w, v1.x, v1.y, v1.z, v1.w};
#pragma unroll
            for (int c = 0; c < 8; c++) {
                acc[0][c] += p0 * vb[c];
                acc[1][c] += p1 * vb[c];
                acc[2][c] += p2 * vb[c];
                acc[3][c] += p3 * vb[c];
            }
        }
        __syncthreads();   // Vs / Ps free

        // prefetch V(kt+1)
        if (kt < qt) {
            const float* vhn = vh + (size_t)(kt + 1) * 64 * (NH * (NND + NVD));
#pragma unroll
            for (int p = 0; p < 8; p++) {
                int c = p * 256 + tid;
                int j = c >> 5, off = (c & 31) * 4;
                cp16(smb + (VS_OFF + j * 132 + off) * 4,
                     vhn + (size_t)j * (NH * (NND + NVD)) + off);
            }
            CP_COMMIT();
        }
    }

    // ---- write output ----
#pragma unroll
    for (int i = 0; i < 4; i++) {
        float inv = 1.f / rl[i];
        int tok = qt0 + ty * 4 + i;
        float* op = ao + ((size_t)(bT + tok) * NH + h) * NVD;
        *(float4*)(op + (tx << 2))      = make_float4(acc[i][0] * inv, acc[i][1] * inv,
                                                      acc[i][2] * inv, acc[i][3] * inv);
        *(float4*)(op + 64 + (tx << 2)) = make_float4(acc[i][4] * inv, acc[i][5] * inv,
                                                      acc[i][6] * inv, acc[i][7] * inv);
    }
}

// ---------------- launch ----------------
extern "C" void kernel_launch(void* const* d_in, const int* in_sizes, int n_in,
                              void* d_out, int out_size)
{
    const float* x    = (const float*)d_in[0];
    const float* fc   = (const float*)d_in[1];
    const float* fs   = (const float*)d_in[2];
    const float* qdw  = (const float*)d_in[3];
    const float* qnw  = (const float*)d_in[4];
    const float* qunw = (const float*)d_in[5];
    const float* qurw = (const float*)d_in[6];
    const float* kdw  = (const float*)d_in[7];
    const float* kvnw = (const float*)d_in[8];
    const float* kuw  = (const float*)d_in[9];
    const float* qhw  = (const float*)d_in[10];
    const float* khw  = (const float*)d_in[11];
    const float* wow  = (const float*)d_in[12];
    float* out = (float*)d_out;

    float *p_cq, *p_qn, *p_qr, *p_q, *p_kvraw, *p_ckv, *p_kr, *p_kv, *p_k, *p_ao, *p_kdwp;
    cudaGetSymbolAddress((void**)&p_cq,    g_cq);
    cudaGetSymbolAddress((void**)&p_qn,    g_qn);
    cudaGetSymbolAddress((void**)&p_qr,    g_qr);
    cudaGetSymbolAddress((void**)&p_q,     g_q);
    cudaGetSymbolAddress((void**)&p_kvraw, g_kvraw);
    cudaGetSymbolAddress((void**)&p_ckv,   g_ckv);
    cudaGetSymbolAddress((void**)&p_kr,    g_kr);
    cudaGetSymbolAddress((void**)&p_kv,    g_kv);
    cudaGetSymbolAddress((void**)&p_k,     g_k);
    cudaGetSymbolAddress((void**)&p_ao,    g_ao);
    cudaGetSymbolAddress((void**)&p_kdwp,  g_kdwpad);

    cudaFuncSetAttribute(gemm_tf32, cudaFuncAttributeMaxDynamicSharedMemorySize,
                         GEMM_SMEM_BYTES);
    cudaFuncSetAttribute(attn_kernel, cudaFuncAttributeMaxDynamicSharedMemorySize,
                         ATTN_SMEM_BYTES);

    // pad kv_down weights once per launch (cheap, deterministic)
    pad_kdw<<<(NDIM * KVP) / 256, 256>>>(kdw, p_kdwp);

    // c_q = x @ q_down_w ; rmsnorm
    gemm_tf32<<<dim3(NQLR / 128, NTOK / 128), 256, GEMM_SMEM_BYTES>>>(x, qdw, p_cq, NTOK, NQLR, NDIM);
    rmsnorm_rows<<<NTOK, 256>>>(p_cq, qnw, NQLR);

    // q projections
    gemm_tf32<<<dim3((NH * NND) / 128, NTOK / 128), 256, GEMM_SMEM_BYTES>>>(p_cq, qunw, p_qn, NTOK, NH * NND, NQLR);
    gemm_tf32<<<dim3((NH * NRD) / 128, NTOK / 128), 256, GEMM_SMEM_BYTES>>>(p_cq, qurw, p_qr, NTOK, NH * NRD, NQLR);

    // kv down (padded to N=640, tf32)
    gemm_tf32<<<dim3(KVP / 128, NTOK / 128), 256, GEMM_SMEM_BYTES>>>(x, p_kdwp, p_kvraw, NTOK, KVP, NDIM);

    // epilogues
    q_build<<<dim3(NH, NTOK), 128>>>(p_qn, p_qr, qhw, fc, fs, p_q);
    kv_post<<<NTOK, 128>>>(p_kvraw, kvnw, fc, fs, p_ckv, p_kr);

    // kv up + k build
    gemm_tf32<<<dim3((NH * (NND + NVD)) / 128, NTOK / 128), 256, GEMM_SMEM_BYTES>>>(p_ckv, kuw, p_kv, NTOK, NH * (NND + NVD), NKVLR);
    k_build<<<dim3(NH, NTOK), 128>>>(p_kv, khw, p_kr, p_k);

    // attention
    attn_kernel<<<dim3(TSEQ / 64, NB * NH), 256, ATTN_SMEM_BYTES>>>(p_q, p_k, p_kv, p_ao);

    // output projection
    gemm_tf32<<<dim3(NDIM / 128, NTOK / 128), 256, GEMM_SMEM_BYTES>>>(p_ao, wow, out, NTOK, NDIM, NH * NVD);
}

// round 13
// speedup vs baseline: 6.0389x; 1.4181x over previous
#include <cuda_runtime.h>
#include <math.h>
#include <stdint.h>

// ---------------- problem constants ----------------
#define NB      2
#define TSEQ    2048
#define NDIM    2048
#define NH      16
#define NQLR    1536
#define NKVLR   512
#define NRD     64
#define NND     128
#define NVD     128
#define NTOK    (NB * TSEQ)        // 4096
#define DQK     (NND + NRD)        // 192
#define KVP     640                 // padded kv_down output width (576 -> 640)
#define EPSV    1e-6f

// ---------------- scratch (no allocations allowed) ----------------
__device__ float g_cq     [(size_t)NTOK * NQLR];
__device__ float g_qn     [(size_t)NTOK * NH * NND];
__device__ float g_qr     [(size_t)NTOK * NH * NRD];
__device__ float g_q      [(size_t)NTOK * NH * DQK];
__device__ float g_kvraw  [(size_t)NTOK * KVP];
__device__ float g_ckv    [(size_t)NTOK * NKVLR];
__device__ float g_kr     [(size_t)NTOK * NRD];
__device__ float g_kv     [(size_t)NTOK * NH * (NND + NVD)];
__device__ float g_k      [(size_t)NTOK * NH * DQK];
__device__ float g_ao     [(size_t)NTOK * NH * NVD];
__device__ float g_kdwpad [(size_t)NDIM * KVP];

// ---------------- helpers ----------------
__device__ __forceinline__ float warp_sum(float v) {
#pragma unroll
    for (int o = 16; o; o >>= 1) v += __shfl_xor_sync(0xffffffffu, v, o);
    return v;
}

__device__ __forceinline__ uint32_t f2tf32(float f) {
    uint32_t r;
    asm("cvt.rna.tf32.f32 %0, %1;" : "=r"(r) : "f"(f));
    return r;
}

__device__ __forceinline__ void mma_tf32(
    float& c0, float& c1, float& c2, float& c3,
    uint32_t a0, uint32_t a1, uint32_t a2, uint32_t a3,
    uint32_t b0, uint32_t b1)
{
    asm volatile(
        "mma.sync.aligned.m16n8k8.row.col.f32.tf32.tf32.f32 "
        "{%0,%1,%2,%3}, {%4,%5,%6,%7}, {%8,%9}, {%0,%1,%2,%3};"
        : "+f"(c0), "+f"(c1), "+f"(c2), "+f"(c3)
        : "r"(a0), "r"(a1), "r"(a2), "r"(a3), "r"(b0), "r"(b1));
}

__device__ __forceinline__ void cp16(uint32_t dst_smem, const void* src) {
    asm volatile("cp.async.cg.shared.global [%0], [%1], 16;\n"
                 :: "r"(dst_smem), "l"(src) : "memory");
}
#define CP_COMMIT() asm volatile("cp.async.commit_group;\n" ::: "memory")
#define CP_WAIT(N)  asm volatile("cp.async.wait_group %0;\n" :: "n"(N) : "memory")

// ============ tf32 tensor-core GEMM, double-buffered ============
#define AS_WORDS 4608            // 128*36
#define BS_WORDS 4352            // 32*136
#define STAGE_WORDS (AS_WORDS + BS_WORDS)
#define GEMM_SMEM_BYTES (2 * STAGE_WORDS * 4)   // 71680

__global__ __launch_bounds__(256, 1) void gemm_tf32(
    const float* __restrict__ A, const float* __restrict__ B,
    float* __restrict__ C, int M, int N, int K)
{
    extern __shared__ uint32_t gsm[];

    const int tid  = threadIdx.x;
    const int wid  = tid >> 5;
    const int lane = tid & 31;
    const int g    = lane >> 2;
    const int tg   = lane & 3;
    const int warp_m = (wid >> 2) * 64;
    const int warp_n = (wid & 3) * 32;

    const int m0 = blockIdx.y << 7;
    const int n0 = blockIdx.x << 7;

    const int ar  = tid >> 3;
    const int akq = (tid & 7) << 2;
    const int br  = tid >> 5;
    const int bc  = (tid & 31) << 2;

    float acc[4][4][4];
#pragma unroll
    for (int mt = 0; mt < 4; mt++)
#pragma unroll
        for (int nt = 0; nt < 4; nt++)
#pragma unroll
            for (int c = 0; c < 4; c++) acc[mt][nt][c] = 0.f;

    const int nk = K >> 5;
    float4 av[4], bv[4];

#pragma unroll
    for (int p = 0; p < 4; p++) {
        av[p] = *(const float4*)(A + (size_t)(m0 + ar + p * 32) * K + akq);
        bv[p] = *(const float4*)(B + (size_t)(br + p * 8) * N + n0 + bc);
    }
    {
        uint32_t* As = gsm;
        uint32_t* Bs = gsm + AS_WORDS;
#pragma unroll
        for (int p = 0; p < 4; p++) {
            uint32_t* da = &As[(ar + p * 32) * 36 + akq];
            da[0] = f2tf32(av[p].x); da[1] = f2tf32(av[p].y);
            da[2] = f2tf32(av[p].z); da[3] = f2tf32(av[p].w);
            uint32_t* db = &Bs[(br + p * 8) * 136 + bc];
            db[0] = f2tf32(bv[p].x); db[1] = f2tf32(bv[p].y);
            db[2] = f2tf32(bv[p].z); db[3] = f2tf32(bv[p].w);
        }
    }

    for (int it = 0; it < nk; it++) {
        uint32_t* As = gsm + (it & 1) * STAGE_WORDS;
        uint32_t* Bs = As + AS_WORDS;
        __syncthreads();

        const bool more = (it + 1 < nk);
        if (more) {
            const int k0 = (it + 1) << 5;
#pragma unroll
            for (int p = 0; p < 4; p++) {
                av[p] = *(const float4*)(A + (size_t)(m0 + ar + p * 32) * K + k0 + akq);
                bv[p] = *(const float4*)(B + (size_t)(k0 + br + p * 8) * N + n0 + bc);
            }
        }

#pragma unroll
        for (int k8 = 0; k8 < 4; k8++) {
            const int kk = k8 * 8;
            uint32_t afr[4][4], bfr[4][2];
#pragma unroll
            for (int mt = 0; mt < 4; mt++) {
                const int m = warp_m + mt * 16;
                afr[mt][0] = As[(m + g) * 36 + kk + tg];
                afr[mt][1] = As[(m + g + 8) * 36 + kk + tg];
                afr[mt][2] = As[(m + g) * 36 + kk + tg + 4];
                afr[mt][3] = As[(m + g + 8) * 36 + kk + tg + 4];
            }
#pragma unroll
            for (int nt = 0; nt < 4; nt++) {
                const int n = warp_n + nt * 8;
                bfr[nt][0] = Bs[(kk + tg) * 136 + n + g];
                bfr[nt][1] = Bs[(kk + tg + 4) * 136 + n + g];
            }
#pragma unroll
            for (int mt = 0; mt < 4; mt++)
#pragma unroll
                for (int nt = 0; nt < 4; nt++)
                    mma_tf32(acc[mt][nt][0], acc[mt][nt][1], acc[mt][nt][2], acc[mt][nt][3],
                             afr[mt][0], afr[mt][1], afr[mt][2], afr[mt][3],
                             bfr[nt][0], bfr[nt][1]);
        }

        if (more) {
            uint32_t* Asn = gsm + ((it + 1) & 1) * STAGE_WORDS;
            uint32_t* Bsn = Asn + AS_WORDS;
#pragma unroll
            for (int p = 0; p < 4; p++) {
                uint32_t* da = &Asn[(ar + p * 32) * 36 + akq];
                da[0] = f2tf32(av[p].x); da[1] = f2tf32(av[p].y);
                da[2] = f2tf32(av[p].z); da[3] = f2tf32(av[p].w);
                uint32_t* db = &Bsn[(br + p * 8) * 136 + bc];
                db[0] = f2tf32(bv[p].x); db[1] = f2tf32(bv[p].y);
                db[2] = f2tf32(bv[p].z); db[3] = f2tf32(bv[p].w);
            }
        }
    }

#pragma unroll
    for (int mt = 0; mt < 4; mt++) {
        const int row = m0 + warp_m + mt * 16 + g;
#pragma unroll
        for (int nt = 0; nt < 4; nt++) {
            const int col = n0 + warp_n + nt * 8 + tg * 2;
            *(float2*)(C + (size_t)row * N + col)       = make_float2(acc[mt][nt][0], acc[mt][nt][1]);
            *(float2*)(C + (size_t)(row + 8) * N + col) = make_float2(acc[mt][nt][2], acc[mt][nt][3]);
        }
    }
}

// ---------------- pad kv_down_w (2048x576) into (2048x640), zero-filled ----------------
__global__ __launch_bounds__(256) void pad_kdw(
    const float* __restrict__ w, float* __restrict__ o)
{
    int idx = blockIdx.x * 256 + threadIdx.x;
    int r = idx / KVP, c = idx - r * KVP;
    o[idx] = (c < NKVLR + NRD) ? w[r * (NKVLR + NRD) + c] : 0.f;
}

// ---------------- row-wise rmsnorm (in place), 256 threads ----------------
__global__ __launch_bounds__(256) void rmsnorm_rows(
    float* __restrict__ x, const float* __restrict__ w, int len)
{
    __shared__ float sb[8];
    float* row = x + (size_t)blockIdx.x * len;
    float ss = 0.f;
    for (int i = threadIdx.x; i < len; i += 256) { float v = row[i]; ss += v * v; }
    ss = warp_sum(ss);
    if ((threadIdx.x & 31) == 0) sb[threadIdx.x >> 5] = ss;
    __syncthreads();
    float tot = 0.f;
#pragma unroll
    for (int i = 0; i < 8; i++) tot += sb[i];
    float sc = rsqrtf(tot / (float)len + EPSV);
    for (int i = threadIdx.x; i < len; i += 256) row[i] = row[i] * sc * w[i];
}

// ---------------- build q ----------------
__global__ __launch_bounds__(128) void q_build(
    const float* __restrict__ qn, const float* __restrict__ qr,
    const float* __restrict__ qhw,
    const float* __restrict__ fc, const float* __restrict__ fs,
    float* __restrict__ q)
{
    __shared__ float sb[4];
    const int token = blockIdx.y, h = blockIdx.x;
    const int t = token & (TSEQ - 1);
    const float* xn = qn + (size_t)token * NH * NND + h * NND;
    float v = xn[threadIdx.x];
    float ss = warp_sum(v * v);
    if ((threadIdx.x & 31) == 0) sb[threadIdx.x >> 5] = ss;
    __syncthreads();
    float tot = sb[0] + sb[1] + sb[2] + sb[3];
    float sc = rsqrtf(tot / (float)NND + EPSV);
    float* qo = q + ((size_t)token * NH + h) * DQK;
    qo[threadIdx.x] = v * sc * qhw[threadIdx.x];
    if (threadIdx.x < NRD / 2) {
        int i = threadIdx.x;
        const float* xr = qr + (size_t)token * NH * NRD + h * NRD;
        float a = xr[2 * i], b = xr[2 * i + 1];
        float c = fc[t * (NRD / 2) + i], s = fs[t * (NRD / 2) + i];
        qo[NND + 2 * i]     = a * c - b * s;
        qo[NND + 2 * i + 1] = a * s + b * c;
    }
}

// ---------------- kv post (reads padded kvraw, stride KVP) ----------------
__global__ __launch_bounds__(128) void kv_post(
    const float* __restrict__ kvraw, const float* __restrict__ kvw,
    const float* __restrict__ fc, const float* __restrict__ fs,
    float* __restrict__ ckv, float* __restrict__ kr)
{
    __shared__ float sb[4];
    const int token = blockIdx.x;
    const int t = token & (TSEQ - 1);
    const float* row = kvraw + (size_t)token * KVP;
    float ss = 0.f;
    for (int i = threadIdx.x; i < NKVLR; i += 128) { float v = row[i]; ss += v * v; }
    ss = warp_sum(ss);
    if ((threadIdx.x & 31) == 0) sb[threadIdx.x >> 5] = ss;
    __syncthreads();
    float tot = sb[0] + sb[1] + sb[2] + sb[3];
    float sc = rsqrtf(tot / (float)NKVLR + EPSV);
    for (int i = threadIdx.x; i < NKVLR; i += 128)
        ckv[(size_t)token * NKVLR + i] = row[i] * sc * kvw[i];
    if (threadIdx.x < NRD / 2) {
        int i = threadIdx.x;
        float a = row[NKVLR + 2 * i], b = row[NKVLR + 2 * i + 1];
        float c = fc[t * (NRD / 2) + i], s = fs[t * (NRD / 2) + i];
        kr[(size_t)token * NRD + 2 * i]     = a * c - b * s;
        kr[(size_t)token * NRD + 2 * i + 1] = a * s + b * c;
    }
}

// ---------------- build k ----------------
__global__ __launch_bounds__(128) void k_build(
    const float* __restrict__ kv, const float* __restrict__ khw,
    const float* __restrict__ kr, float* __restrict__ k)
{
    __shared__ float sb[4];
    const int token = blockIdx.y, h = blockIdx.x;
    const float* kn = kv + ((size_t)token * NH + h) * (NND + NVD);
    float v = kn[threadIdx.x];
    float ss = warp_sum(v * v);
    if ((threadIdx.x & 31) == 0) sb[threadIdx.x >> 5] = ss;
    __syncthreads();
    float tot = sb[0] + sb[1] + sb[2] + sb[3];
    float sc = rsqrtf(tot / (float)NND + EPSV);
    float* ko = k + ((size_t)token * NH + h) * DQK;
    ko[threadIdx.x] = v * sc * khw[threadIdx.x];
    if (threadIdx.x < NRD) ko[NND + threadIdx.x] = kr[(size_t)token * NRD + threadIdx.x];
}

// ============ causal flash attention v5: tf32 MMA for QK^T and PV ============
// grid: (TSEQ/64, B*H), block 256 = 8 warps.
// Warp tiles: scores 16 rows x 32 keys (warp_m=(wid>>1)*16, half=(wid&1));
//             PV 16 rows x 64 cols (same warp_m, col half = (wid&1)*64).
// Thread fragment rows: row0 = warp_m+g, row1 = row0+8 (g = lane>>2, tg = lane&3).
// Smem (floats): Qs[64][196] @0 (tf32 bits after in-place cvt), Ks[2][64][196] @12544,
//   Vs[64][136] @37632, Ps[64][68] @46336 (tf32 bits), Mx[128] @50688, Sx[128] @50816.
#define QS_OFF 0
#define KS_OFF 12544
#define KS_SZ  12544
#define VS_OFF 37632
#define PS_OFF 46336
#define MX_OFF 50688
#define SX_OFF 50816
#define ATTN_SMEM_BYTES (50944 * 4)   // 203776

__global__ __launch_bounds__(256) void attn_kernel(
    const float* __restrict__ q, const float* __restrict__ k,
    const float* __restrict__ kv, float* __restrict__ ao)
{
    extern __shared__ float sm[];
    float* Qs = sm + QS_OFF;
    float* Vs = sm + VS_OFF;
    float* Ps = sm + PS_OFF;
    float* Mx = sm + MX_OFF;
    float* Sx = sm + SX_OFF;
    const uint32_t smb = (uint32_t)__cvta_generic_to_shared(sm);

    const int tid  = threadIdx.x;
    const int wid  = tid >> 5;
    const int lane = tid & 31;
    const int g    = lane >> 2;
    const int tg   = lane & 3;
    const int warp_m = (wid >> 1) * 16;
    const int half   = wid & 1;           // key half for scores, col half for PV
    const int row0 = warp_m + g;
    const int row1 = row0 + 8;

    const int qt = (int)gridDim.x - 1 - (int)blockIdx.x;
    const int bh = blockIdx.y;
    const int b = bh >> 4, h = bh & 15;
    const int qt0 = qt << 6;
    const int bT = b * TSEQ;
    const float SCALE = 0.07216878364870322f;

    const float* qh = q  + ((size_t)(bT + qt0) * NH + h) * DQK;
    const float* vh = kv + ((size_t)bT * NH + h) * (NND + NVD) + NND;

    // loader indices: 4 threads per row, 12 quads each (48 quads = 192 floats/row)
    const int lrow = tid >> 2;
    const int lq0  = (tid & 3) * 12;

    // ---- prologue: async Q + K0 (group), V0 (group) ----
#pragma unroll
    for (int p = 0; p < 12; p++) {
        int quad = lq0 + p;
        cp16(smb + (QS_OFF + lrow * 196 + quad * 4) * 4,
             qh + (size_t)lrow * (NH * DQK) + quad * 4);
    }
    {
        const float* kh0 = k + ((size_t)bT * NH + h) * DQK;
#pragma unroll
        for (int p = 0; p < 12; p++) {
            int quad = lq0 + p;
            cp16(smb + (KS_OFF + lrow * 196 + quad * 4) * 4,
                 kh0 + (size_t)lrow * (NH * DQK) + quad * 4);
        }
    }
    CP_COMMIT();   // group: Q + K0
#pragma unroll
    for (int p = 0; p < 8; p++) {
        int c = p * 256 + tid;
        int j = c >> 5, off = (c & 31) * 4;
        cp16(smb + (VS_OFF + j * 136 + off) * 4,
             vh + (size_t)j * (NH * (NND + NVD)) + off);
    }
    CP_COMMIT();   // group: V0

    float rm0 = -1e30f, rm1 = -1e30f, rl0 = 0.f, rl1 = 0.f;
    float acc[8][4];   // 8 n-subtiles of PV output (cols half*64 + nt*8)
#pragma unroll
    for (int nt = 0; nt < 8; nt++)
#pragma unroll
        for (int c = 0; c < 4; c++) acc[nt][c] = 0.f;

    for (int kt = 0; kt <= qt; kt++) {
        CP_WAIT(1);
        __syncthreads();   // K(kt) (and Q at kt=0) visible

        if (kt == 0) {
            // in-place tf32 conversion of Q (12544 words incl. pad)
            for (int i = tid; i < 12544; i += 256)
                Qs[i] = __uint_as_float(f2tf32(Qs[i]));
            __syncthreads();
        }

        // prefetch K(kt+1) into other buffer
        if (kt < qt) {
            const float* khn = k + ((size_t)(bT + (kt + 1) * 64) * NH + h) * DQK;
            const uint32_t kdst = smb + (KS_OFF + ((kt + 1) & 1) * KS_SZ) * 4;
#pragma unroll
            for (int p = 0; p < 12; p++) {
                int quad = lq0 + p;
                cp16(kdst + (lrow * 196 + quad * 4) * 4,
                     khn + (size_t)lrow * (NH * DQK) + quad * 4);
            }
            CP_COMMIT();
        }

        const float* Ks = sm + KS_OFF + (kt & 1) * KS_SZ;
        const int warp_n = half * 32;

        // ---- scores via MMA: 16x32 per warp, k=192 ----
        float s[4][4];
#pragma unroll
        for (int nt = 0; nt < 4; nt++)
#pragma unroll
            for (int c = 0; c < 4; c++) s[nt][c] = 0.f;

#pragma unroll 4
        for (int ks = 0; ks < 24; ks++) {
            const int kk = ks * 8;
            uint32_t a0 = __float_as_uint(Qs[row0 * 196 + kk + tg]);
            uint32_t a1 = __float_as_uint(Qs[row1 * 196 + kk + tg]);
            uint32_t a2 = __float_as_uint(Qs[row0 * 196 + kk + tg + 4]);
            uint32_t a3 = __float_as_uint(Qs[row1 * 196 + kk + tg + 4]);
#pragma unroll
            for (int nt = 0; nt < 4; nt++) {
                const int n = warp_n + nt * 8 + g;
                uint32_t b0 = f2tf32(Ks[n * 196 + kk + tg]);
                uint32_t b1 = f2tf32(Ks[n * 196 + kk + tg + 4]);
                mma_tf32(s[nt][0], s[nt][1], s[nt][2], s[nt][3],
                         a0, a1, a2, a3, b0, b1);
            }
        }

        // scale + causal mask (diag tile)
#pragma unroll
        for (int nt = 0; nt < 4; nt++)
#pragma unroll
            for (int c = 0; c < 4; c++) s[nt][c] *= SCALE;
        if (kt == qt) {
#pragma unroll
            for (int nt = 0; nt < 4; nt++) {
                int col = warp_n + nt * 8 + 2 * tg;
                if (col     > row0) s[nt][0] = -1e30f;
                if (col + 1 > row0) s[nt][1] = -1e30f;
                if (col     > row1) s[nt][2] = -1e30f;
                if (col + 1 > row1) s[nt][3] = -1e30f;
            }
        }

        // ---- row max: tg-shuffle then cross-half smem exchange ----
        float m0p = -1e30f, m1p = -1e30f;
#pragma unroll
        for (int nt = 0; nt < 4; nt++) {
            m0p = fmaxf(m0p, fmaxf(s[nt][0], s[nt][1]));
            m1p = fmaxf(m1p, fmaxf(s[nt][2], s[nt][3]));
        }
        m0p = fmaxf(m0p, __shfl_xor_sync(0xffffffffu, m0p, 1));
        m0p = fmaxf(m0p, __shfl_xor_sync(0xffffffffu, m0p, 2));
        m1p = fmaxf(m1p, __shfl_xor_sync(0xffffffffu, m1p, 1));
        m1p = fmaxf(m1p, __shfl_xor_sync(0xffffffffu, m1p, 2));
        if (tg == 0) {
            Mx[half * 64 + row0] = m0p;
            Mx[half * 64 + row1] = m1p;
        }
        __syncthreads();

        float mn0 = fmaxf(rm0, fmaxf(Mx[row0], Mx[64 + row0]));
        float mn1 = fmaxf(rm1, fmaxf(Mx[row1], Mx[64 + row1]));
        float corr0 = __expf(rm0 - mn0);
        float corr1 = __expf(rm1 - mn1);
        rm0 = mn0; rm1 = mn1;

        // exp + partial sums + store P (tf32 bits) to smem
        float s0p = 0.f, s1p = 0.f;
#pragma unroll
        for (int nt = 0; nt < 4; nt++) {
            float e0 = __expf(s[nt][0] - mn0);
            float e1 = __expf(s[nt][1] - mn0);
            float e2 = __expf(s[nt][2] - mn1);
            float e3 = __expf(s[nt][3] - mn1);
            s0p += e0 + e1;
            s1p += e2 + e3;
            int col = warp_n + nt * 8 + 2 * tg;
            *(float2*)&Ps[row0 * 68 + col] =
                make_float2(__uint_as_float(f2tf32(e0)), __uint_as_float(f2tf32(e1)));
            *(float2*)&Ps[row1 * 68 + col] =
                make_float2(__uint_as_float(f2tf32(e2)), __uint_as_float(f2tf32(e3)));
        }
        s0p += __shfl_xor_sync(0xffffffffu, s0p, 1);
        s0p += __shfl_xor_sync(0xffffffffu, s0p, 2);
        s1p += __shfl_xor_sync(0xffffffffu, s1p, 1);
        s1p += __shfl_xor_sync(0xffffffffu, s1p, 2);
        if (tg == 0) {
            Sx[half * 64 + row0] = s0p;
            Sx[half * 64 + row1] = s1p;
        }

        // rescale PV accumulators (rows row0 -> c0,c1; row1 -> c2,c3)
#pragma unroll
        for (int nt = 0; nt < 8; nt++) {
            acc[nt][0] *= corr0; acc[nt][1] *= corr0;
            acc[nt][2] *= corr1; acc[nt][3] *= corr1;
        }

        // retire V(kt); publish Ps/Sx
        if (kt < qt) { CP_WAIT(1); } else { CP_WAIT(0); }
        __syncthreads();

        rl0 = rl0 * corr0 + Sx[row0] + Sx[64 + row0];
        rl1 = rl1 * corr1 + Sx[row1] + Sx[64 + row1];

        // ---- PV via MMA: 16 rows x 64 cols per warp, k=64 keys ----
#pragma unroll
        for (int ks = 0; ks < 8; ks++) {
            const int kk = ks * 8;
            uint32_t a0 = __float_as_uint(Ps[row0 * 68 + kk + tg]);
            uint32_t a1 = __float_as_uint(Ps[row1 * 68 + kk + tg]);
            uint32_t a2 = __float_as_uint(Ps[row0 * 68 + kk + tg + 4]);
            uint32_t a3 = __float_as_uint(Ps[row1 * 68 + kk + tg + 4]);
#pragma unroll
            for (int nt = 0; nt < 8; nt++) {
                const int n = half * 64 + nt * 8 + g;
                uint32_t b0 = f2tf32(Vs[(kk + tg) * 136 + n]);
                uint32_t b1 = f2tf32(Vs[(kk + tg + 4) * 136 + n]);
                mma_tf32(acc[nt][0], acc[nt][1], acc[nt][2], acc[nt][3],
                         a0, a1, a2, a3, b0, b1);
            }
        }
        __syncthreads();   // PV reads of Vs/Ps done

        // prefetch V(kt+1)
        if (kt < qt) {
            const float* vhn = vh + (size_t)(kt + 1) * 64 * (NH * (NND + NVD));
#pragma unroll
            for (int p = 0; p < 8; p++) {
                int c = p * 256 + tid;
                int j = c >> 5, off = (c & 31) * 4;
                cp16(smb + (VS_OFF + j * 136 + off) * 4,
                     vhn + (size_t)j * (NH * (NND + NVD)) + off);
            }
            CP_COMMIT();
        }
    }

    // ---- write output ----
    const float inv0 = 1.f / rl0;
    const float inv1 = 1.f / rl1;
    float* op0 = ao + ((size_t)(bT + qt0 + row0) * NH + h) * NVD;
    float* op1 = ao + ((size_t)(bT + qt0 + row1) * NH + h) * NVD;
#pragma unroll
    for (int nt = 0; nt < 8; nt++) {
        int col = half * 64 + nt * 8 + 2 * tg;
        *(float2*)(op0 + col) = make_float2(acc[nt][0] * inv0, acc[nt][1] * inv0);
        *(float2*)(op1 + col) = make_float2(acc[nt][2] * inv1, acc[nt][3] * inv1);
    }
}

// ---------------- launch ----------------
extern "C" void kernel_launch(void* const* d_in, const int* in_sizes, int n_in,
                              void* d_out, int out_size)
{
    const float* x    = (const float*)d_in[0];
    const float* fc   = (const float*)d_in[1];
    const float* fs   = (const float*)d_in[2];
    const float* qdw  = (const float*)d_in[3];
    const float* qnw  = (const float*)d_in[4];
    const float* qunw = (const float*)d_in[5];
    const float* qurw = (const float*)d_in[6];
    const float* kdw  = (const float*)d_in[7];
    const float* kvnw = (const float*)d_in[8];
    const float* kuw  = (const float*)d_in[9];
    const float* qhw  = (const float*)d_in[10];
    const float* khw  = (const float*)d_in[11];
    const float* wow  = (const float*)d_in[12];
    float* out = (float*)d_out;

    float *p_cq, *p_qn, *p_qr, *p_q, *p_kvraw, *p_ckv, *p_kr, *p_kv, *p_k, *p_ao, *p_kdwp;
    cudaGetSymbolAddress((void**)&p_cq,    g_cq);
    cudaGetSymbolAddress((void**)&p_qn,    g_qn);
    cudaGetSymbolAddress((void**)&p_qr,    g_qr);
    cudaGetSymbolAddress((void**)&p_q,     g_q);
    cudaGetSymbolAddress((void**)&p_kvraw, g_kvraw);
    cudaGetSymbolAddress((void**)&p_ckv,   g_ckv);
    cudaGetSymbolAddress((void**)&p_kr,    g_kr);
    cudaGetSymbolAddress((void**)&p_kv,    g_kv);
    cudaGetSymbolAddress((void**)&p_k,     g_k);
    cudaGetSymbolAddress((void**)&p_ao,    g_ao);
    cudaGetSymbolAddress((void**)&p_kdwp,  g_kdwpad);

    cudaFuncSetAttribute(gemm_tf32, cudaFuncAttributeMaxDynamicSharedMemorySize,
                         GEMM_SMEM_BYTES);
    cudaFuncSetAttribute(attn_kernel, cudaFuncAttributeMaxDynamicSharedMemorySize,
                         ATTN_SMEM_BYTES);

    pad_kdw<<<(NDIM * KVP) / 256, 256>>>(kdw, p_kdwp);

    // c_q = x @ q_down_w ; rmsnorm
    gemm_tf32<<<dim3(NQLR / 128, NTOK / 128), 256, GEMM_SMEM_BYTES>>>(x, qdw, p_cq, NTOK, NQLR, NDIM);
    rmsnorm_rows<<<NTOK, 256>>>(p_cq, qnw, NQLR);

    // q projections
    gemm_tf32<<<dim3((NH * NND) / 128, NTOK / 128), 256, GEMM_SMEM_BYTES>>>(p_cq, qunw, p_qn, NTOK, NH * NND, NQLR);
    gemm_tf32<<<dim3((NH * NRD) / 128, NTOK / 128), 256, GEMM_SMEM_BYTES>>>(p_cq, qurw, p_qr, NTOK, NH * NRD, NQLR);

    // kv down (padded to N=640, tf32)
    gemm_tf32<<<dim3(KVP / 128, NTOK / 128), 256, GEMM_SMEM_BYTES>>>(x, p_kdwp, p_kvraw, NTOK, KVP, NDIM);

    // epilogues
    q_build<<<dim3(NH, NTOK), 128>>>(p_qn, p_qr, qhw, fc, fs, p_q);
    kv_post<<<NTOK, 128>>>(p_kvraw, kvnw, fc, fs, p_ckv, p_kr);

    // kv up + k build
    gemm_tf32<<<dim3((NH * (NND + NVD)) / 128, NTOK / 128), 256, GEMM_SMEM_BYTES>>>(p_ckv, kuw, p_kv, NTOK, NH * (NND + NVD), NKVLR);
    k_build<<<dim3(NH, NTOK), 128>>>(p_kv, khw, p_kr, p_k);

    // attention
    attn_kernel<<<dim3(TSEQ / 64, NB * NH), 256, ATTN_SMEM_BYTES>>>(p_q, p_k, p_kv, p_ao);

    // output projection
    gemm_tf32<<<dim3(NDIM / 128, NTOK / 128), 256, GEMM_SMEM_BYTES>>>(p_ao, wow, out, NTOK, NDIM, NH * NVD);
}